// round 13
// baseline (speedup 1.0000x reference)
#include <cuda_runtime.h>
#include <cstdint>

#define BATCH 16
#define NN 1408
#define DIM 256
#define HD 64
#define BN (BATCH*NN)
#define KSEL 211
#define NTJ 22
#define NTI 11
#define NPB (NTI*NTJ*BATCH*4)
#define SZ ((size_t)BATCH*NN*NN)

typedef unsigned long long u64;

__device__ __align__(16) float g_z[(size_t)BN*DIM];
__device__ __align__(16) float g_h1[(size_t)BN*128];
__device__ __align__(16) float g_sq[4*BN];
__device__ __align__(16) float g_dist4[4*SZ];
__device__ __align__(16) float g_thr4[4*BN];
__device__ __align__(16) int   g_tie4[4*BN];
__device__ __align__(16) float g_score[BN];
__device__ __align__(16) float g_w[3*BN];
__device__ __align__(16) float g_projT[DIM*DIM];
__device__ __align__(16) float g_w1T[DIM*128];
__device__ __align__(16) float g_partial[NPB];
__device__ float g_inv4[4];

__device__ __forceinline__ u64 pack2(float lo, float hi){
    u64 r; asm("mov.b64 %0, {%1, %2};" : "=l"(r) : "f"(lo), "f"(hi)); return r;
}
__device__ __forceinline__ u64 fma2(u64 a, u64 b, u64 c){
    u64 d; asm("fma.rn.f32x2 %0, %1, %2, %3;" : "=l"(d) : "l"(a), "l"(b), "l"(c)); return d;
}
__device__ __forceinline__ float2 unpack2(u64 v){
    float2 f; asm("mov.b64 {%0, %1}, %2;" : "=f"(f.x), "=f"(f.y) : "l"(v)); return f;
}

__global__ void prep_kernel(const float* __restrict__ proj_w,
                            const float* __restrict__ score_w1) {
    int idx = blockIdx.x * 256 + threadIdx.x;
    int c = idx >> 8, k = idx & 255;
    g_projT[k * DIM + c] = proj_w[idx];
    if (idx < 128 * 256) g_w1T[k * 128 + c] = score_w1[idx];
}

template<int NOUT, bool IS_Z>
__global__ void __launch_bounds__(256, 4) gemm_kernel(const float* __restrict__ A,
                                                      const float* __restrict__ bias) {
    const float* Bt = IS_Z ? g_projT : g_w1T;
    float*       C  = IS_Z ? g_z     : g_h1;
    __shared__ __align__(16) float As[32][68];
    __shared__ __align__(16) float Bs[32][68];
    const int t = threadIdx.x, tx = t & 15, ty = t >> 4;
    const int m0 = blockIdx.y * 64, n0 = blockIdx.x * 64;
    u64 acc[4][2] = {};
    for (int k0 = 0; k0 < DIM; k0 += 32) {
        #pragma unroll
        for (int i = 0; i < 8; i++) {
            int e = t + i * 256, r = e >> 5, k = e & 31;
            As[k][r] = A[(size_t)(m0 + r) * DIM + k0 + k];
        }
        #pragma unroll
        for (int i = 0; i < 8; i++) {
            int e = t + i * 256, c = e & 63, k = e >> 6;
            Bs[k][c] = Bt[(size_t)(k0 + k) * NOUT + n0 + c];
        }
        __syncthreads();
        #pragma unroll 8
        for (int k = 0; k < 32; k++) {
            float4 bf = *reinterpret_cast<const float4*>(&Bs[k][tx*4]);
            float4 af = *reinterpret_cast<const float4*>(&As[k][ty*4]);
            u64 b01 = pack2(bf.x, bf.y), b23 = pack2(bf.z, bf.w);
            const float av[4] = {af.x, af.y, af.z, af.w};
            #pragma unroll
            for (int i = 0; i < 4; i++) {
                u64 aa = pack2(av[i], av[i]);
                acc[i][0] = fma2(aa, b01, acc[i][0]);
                acc[i][1] = fma2(aa, b23, acc[i][1]);
            }
        }
        __syncthreads();
    }
    #pragma unroll
    for (int i = 0; i < 4; i++) {
        float2 v01 = unpack2(acc[i][0]), v23 = unpack2(acc[i][1]);
        float v[4] = {v01.x, v01.y, v23.x, v23.y};
        float4 o;
        #pragma unroll
        for (int j = 0; j < 4; j++) {
            float val = v[j];
            if (!IS_Z) {
                val += bias[n0 + tx*4 + j];
                val = 0.5f * val * (1.0f + erff(val * 0.70710678118654752f));
            }
            ((float*)&o)[j] = val;
        }
        *reinterpret_cast<float4*>(&C[(size_t)(m0 + ty*4 + i) * NOUT + n0 + tx*4]) = o;
        if (IS_Z) {
            float sq = v[0]*v[0] + v[1]*v[1] + v[2]*v[2] + v[3]*v[3];
            #pragma unroll
            for (int off = 8; off; off >>= 1)
                sq += __shfl_down_sync(0xffffffffu, sq, off, 16);
            if (tx == 0) g_sq[blockIdx.x * BN + m0 + ty*4 + i] = sq;
        }
    }
}

__global__ void score_kernel(const float* __restrict__ w2, const float* __restrict__ b2) {
    const int n = blockIdx.x, t = threadIdx.x;
    float s = g_h1[(size_t)n * 128 + t] * w2[t];
    #pragma unroll
    for (int off = 16; off; off >>= 1) s += __shfl_down_sync(0xffffffffu, s, off);
    __shared__ float sw[4];
    if ((t & 31) == 0) sw[t >> 5] = s;
    __syncthreads();
    if (t == 0) {
        float v = sw[0] + sw[1] + sw[2] + sw[3] + b2[0];
        g_score[n] = 1.0f / (1.0f + expf(-v));
    }
}

__global__ void gate_kernel(const float* __restrict__ x, const float* __restrict__ gw,
                            const float* __restrict__ gb) {
    const int lane = threadIdx.x & 31;
    const int n = blockIdx.x * 8 + (threadIdx.x >> 5);
    const float* xr = x + (size_t)n * DIM;
    float a0 = 0.f, a1 = 0.f, a2 = 0.f;
    for (int k = lane; k < DIM; k += 32) {
        float xv = xr[k];
        a0 += xv * gw[k]; a1 += xv * gw[DIM + k]; a2 += xv * gw[2*DIM + k];
    }
    #pragma unroll
    for (int off = 16; off; off >>= 1) {
        a0 += __shfl_down_sync(0xffffffffu, a0, off);
        a1 += __shfl_down_sync(0xffffffffu, a1, off);
        a2 += __shfl_down_sync(0xffffffffu, a2, off);
    }
    if (lane == 0) {
        float p0 = a0 + gb[0], p1 = a1 + gb[1], p2 = a2 + gb[2];
        float mx = fmaxf(p0, fmaxf(p1, p2));
        float e0 = expf(p0 - mx), e1 = expf(p1 - mx), e2 = expf(p2 - mx);
        float es = e0 + e1 + e2;
        float pr[3] = {e0/es, e1/es, e2/es};
        int pos[3];
        #pragma unroll
        for (int a = 0; a < 3; a++) {
            int c = 0;
            #pragma unroll
            for (int b = 0; b < 3; b++)
                c += ((pr[b] > pr[a]) || (pr[b] == pr[a] && b < a)) ? 1 : 0;
            pos[a] = c;
        }
        float sp[3];
        #pragma unroll
        for (int a = 0; a < 3; a++) sp[pos[a]] = pr[a];
        float c1 = sp[0] + sp[1];
        float c2 = c1 + sp[2];
        if (!((c1 - sp[1]) < 0.85f)) sp[1] = 0.f;
        if (!((c2 - sp[2]) < 0.85f)) sp[2] = 0.f;
        float w0 = sp[pos[0]], w1 = sp[pos[1]], w2v = sp[pos[2]];
        float scale = 1.0f / (w0 + w1 + w2v + 1e-8f);
        g_w[n]        = w0  * scale;
        g_w[BN + n]   = w1  * scale;
        g_w[2*BN + n] = w2v * scale;
    }
}

// gram v2: 128x64 block tile, 4x8 per thread, symmetric half (tj >= 2*ti),
// mirror via natural-layout smem buffer with conflict-audited access.
__global__ void __launch_bounds__(256, 3) gram_kernel() {
    const int tj = blockIdx.x, ti = blockIdx.y;      // cols tile 64, rows tile 128
    const int z = blockIdx.z, h = z >> 4, b = z & 15;
    const int pidx = z * (NTI*NTJ) + ti * NTJ + tj;
    if (tj < 2*ti) { if (threadIdx.x == 0) g_partial[pidx] = 0.f; return; }
    __shared__ __align__(16) float Az[64*132];       // [k][row], stride 132
    __shared__ __align__(16) float Bz[64*68];        // [k][col], stride 68
    __shared__ float sred[8];
    const int t = threadIdx.x, tx = t & 7, ty = t >> 3;
    const int i0 = ti*128, j0 = tj*64;
    const float* zb = g_z + (size_t)b * NN * DIM + h * HD;
    // A tile: 128 rows x 64 k. lane-stride-1 rows -> conflict-free STS; LDG scattered (L2-hit)
    #pragma unroll
    for (int it = 0; it < 8; it++) {
        int e = t + it * 256;                // [0,2048)
        int r = e & 127, k4 = (e >> 7) * 4;
        float4 v = *reinterpret_cast<const float4*>(&zb[(size_t)(i0 + r) * DIM + k4]);
        Az[k4*132 + r] = v.x; Az[(k4+1)*132 + r] = v.y;
        Az[(k4+2)*132 + r] = v.z; Az[(k4+3)*132 + r] = v.w;
    }
    // B tile: 64 cols x 64 k
    #pragma unroll
    for (int it = 0; it < 4; it++) {
        int e = t + it * 256;                // [0,1024)
        int c = e & 63, k4 = (e >> 6) * 4;
        float4 v = *reinterpret_cast<const float4*>(&zb[(size_t)(j0 + c) * DIM + k4]);
        Bz[k4*68 + c] = v.x; Bz[(k4+1)*68 + c] = v.y;
        Bz[(k4+2)*68 + c] = v.z; Bz[(k4+3)*68 + c] = v.w;
    }
    __syncthreads();
    u64 acc[4][4] = {};
    #pragma unroll 8
    for (int k = 0; k < 64; k++) {
        float4 b0 = *reinterpret_cast<const float4*>(&Bz[k*68 + tx*8]);
        float4 b1 = *reinterpret_cast<const float4*>(&Bz[k*68 + tx*8 + 4]);
        float4 af = *reinterpret_cast<const float4*>(&Az[k*132 + ty*4]);
        u64 b01 = pack2(b0.x, b0.y), b23 = pack2(b0.z, b0.w);
        u64 b45 = pack2(b1.x, b1.y), b67 = pack2(b1.z, b1.w);
        const float av[4] = {af.x, af.y, af.z, af.w};
        #pragma unroll
        for (int i = 0; i < 4; i++) {
            u64 aa = pack2(av[i], av[i]);
            acc[i][0] = fma2(aa, b01, acc[i][0]);
            acc[i][1] = fma2(aa, b23, acc[i][1]);
            acc[i][2] = fma2(aa, b45, acc[i][2]);
            acc[i][3] = fma2(aa, b67, acc[i][3]);
        }
    }
    const float* sqb = g_sq + h * BN + b * NN;
    float* dbase = g_dist4 + (size_t)h * SZ + (size_t)b * NN * NN;
    const bool pure = (tj >= 2*ti + 2);      // whole tile strictly above diagonal
    float sqj[8];
    #pragma unroll
    for (int j = 0; j < 8; j++) sqj[j] = sqb[j0 + tx*8 + j];
    float lsum = 0.f;
    float dval[4][8];
    #pragma unroll
    for (int i = 0; i < 4; i++) {
        int gi = i0 + ty*4 + i;
        float sqi = sqb[gi];
        #pragma unroll
        for (int q = 0; q < 4; q++) {
            float2 dd = unpack2(acc[i][q]);
            float d2a = sqi + sqj[2*q]   - 2.0f * dd.x;
            float d2b = sqi + sqj[2*q+1] - 2.0f * dd.y;
            dval[i][2*q]   = (d2a > 0.f) ? sqrtf(d2a) : 0.f;
            dval[i][2*q+1] = (d2b > 0.f) ? sqrtf(d2b) : 0.f;
        }
        if (pure) {
            #pragma unroll
            for (int j = 0; j < 8; j++) lsum += 2.0f * dval[i][j];
            *reinterpret_cast<float4*>(&dbase[(size_t)gi * NN + j0 + tx*8]) =
                make_float4(dval[i][0], dval[i][1], dval[i][2], dval[i][3]);
            *reinterpret_cast<float4*>(&dbase[(size_t)gi * NN + j0 + tx*8 + 4]) =
                make_float4(dval[i][4], dval[i][5], dval[i][6], dval[i][7]);
        } else {
            #pragma unroll
            for (int j = 0; j < 8; j++) {
                int gj = j0 + tx*8 + j;
                float wgt = (gj > gi) ? 2.0f : ((gj == gi) ? 1.0f : 0.0f);
                lsum += wgt * dval[i][j];
                if (gj >= gi) dbase[(size_t)gi * NN + gj] = dval[i][j];
            }
        }
    }
    #pragma unroll
    for (int off = 16; off; off >>= 1) lsum += __shfl_down_sync(0xffffffffu, lsum, off);
    if ((t & 31) == 0) sred[t >> 5] = lsum;
    __syncthreads();                          // Az reads done; sred visible
    // stage natural-layout copy for the mirror write: Mz[r][c], stride 65 (fits in Az)
    float* Mz = Az;
    #pragma unroll
    for (int i = 0; i < 4; i++)
        #pragma unroll
        for (int j = 0; j < 8; j++)
            Mz[(ty*4 + i) * 65 + (tx*8 + j)] = dval[i][j];
    __syncthreads();
    // mirror write: rows (j0..j0+64) x cols (i0..i0+128), coalesced, conflict-free reads
    #pragma unroll
    for (int it = 0; it < 32; it++) {
        int idx = t + it * 256;               // [0,8192)
        int outRow = idx >> 7, outCol = idx & 127;
        float v = Mz[outCol * 65 + outRow];
        int dstRow = j0 + outRow, dstCol = i0 + outCol;
        if (pure || dstRow > dstCol)
            dbase[(size_t)dstRow * NN + dstCol] = v;
    }
    if (t == 0) {
        float s = 0.f;
        #pragma unroll
        for (int wv = 0; wv < 8; wv++) s += sred[wv];
        g_partial[pidx] = s;
    }
}

__global__ void reduce_kernel() {
    const int h = blockIdx.x;
    __shared__ float s[256];
    float a = 0.f;
    for (int i = threadIdx.x; i < NTI*NTJ*BATCH; i += 256)
        a += g_partial[h * (NTI*NTJ*BATCH) + i];
    s[threadIdx.x] = a;
    __syncthreads();
    for (int off = 128; off; off >>= 1) {
        if (threadIdx.x < off) s[threadIdx.x] += s[threadIdx.x + off];
        __syncthreads();
    }
    if (threadIdx.x == 0) {
        float mean = s[0] / 31719424.0f;
        g_inv4[h] = 1.0f / (2.0f * mean * mean + 1e-8f);
    }
}

// hist8 radix select v2 (R11: 408us)
__global__ void select_kernel() {
    __shared__ unsigned rowv[NN];
    __shared__ unsigned hist8[8][256];
    __shared__ unsigned wsum[8];
    __shared__ int sh[4];
    const int t = threadIdx.x, w = t >> 5, lane = t & 31;
    const int row = blockIdx.x;
    const int h = 3 - blockIdx.y;
    const float* dp = g_dist4 + (size_t)h * SZ + (size_t)row * NN;
    unsigned myv[6];
    #pragma unroll
    for (int i = 0; i < 6; i++) {
        int j = t + i * 256;
        unsigned u = (j < NN) ? __float_as_uint(dp[j]) : 0xFFFFFFFFu;
        myv[i] = u;
        if (j < NN) rowv[j] = u;
    }
    #pragma unroll
    for (int i = 0; i < 8; i++) hist8[i][t] = 0;
    __syncthreads();
    unsigned prefix = 0; int rem = KSEL, ceq = 0;
    #pragma unroll
    for (int pass = 0; pass < 4; pass++) {
        const int shift = 24 - 8 * pass;
        const unsigned himask = pass ? (0xFFFFFFFFu << (shift + 8)) : 0u;
        #pragma unroll
        for (int i = 0; i < 6; i++) {
            unsigned u = myv[i];
            if (((u & himask) == prefix) && (t + i * 256 < NN))
                atomicAdd(&hist8[w][(u >> shift) & 255u], 1u);
        }
        __syncthreads();
        unsigned hv[8], v = 0;
        #pragma unroll
        for (int i = 0; i < 8; i++) { hv[i] = hist8[i][t]; v += hv[i]; }
        if (v) {
            #pragma unroll
            for (int i = 0; i < 8; i++) if (hv[i]) hist8[i][t] = 0;
        }
        unsigned incl = v;
        #pragma unroll
        for (int o = 1; o < 32; o <<= 1) {
            unsigned nb = __shfl_up_sync(0xffffffffu, incl, o);
            if (lane >= o) incl += nb;
        }
        if (lane == 31) wsum[w] = incl;
        __syncthreads();
        unsigned wo = 0;
        #pragma unroll
        for (int i = 0; i < 8; i++) if (i < w) wo += wsum[i];
        incl += wo;
        unsigned excl = incl - v;
        if (excl < (unsigned)rem && (unsigned)rem <= incl) {
            sh[0] = t; sh[1] = rem - (int)excl; sh[2] = (int)v;
        }
        __syncthreads();
        prefix |= ((unsigned)sh[0]) << shift;
        rem = sh[1]; ceq = sh[2];
    }
    int tieIdx;
    if (rem >= ceq) {
        tieIdx = 0x7fffffff;
    } else {
        if (t == 0) {
            int c = 0, tiv = NN;
            for (int j = 0; j < NN; j++)
                if (rowv[j] == prefix) { if (++c == rem) { tiv = j; break; } }
            sh[3] = tiv;
        }
        __syncthreads();
        tieIdx = sh[3];
    }
    if (t == 0) { g_thr4[h*BN + row] = __uint_as_float(prefix); g_tie4[h*BN + row] = tieIdx; }
}

__global__ void combine_kernel(float* __restrict__ out,
                               const float* __restrict__ tmask,
                               const float* __restrict__ smask,
                               const float* __restrict__ thrp) {
    const int i = blockIdx.x, b = blockIdx.y;
    const int row = b * NN + i;
    const int j0 = threadIdx.x * 4;
    const size_t roff = (size_t)b * NN * NN + (size_t)i * NN + j0;
    float adj[4] = {0.f, 0.f, 0.f, 0.f};
    #pragma unroll
    for (int h = 0; h < 4; h++) {
        const float inv  = g_inv4[h];
        const float thri = g_thr4[h*BN + row];
        const int   tiei = g_tie4[h*BN + row];
        const float4 d4  = *reinterpret_cast<const float4*>(&g_dist4[(size_t)h * SZ + roff]);
        const float4 tj4 = *reinterpret_cast<const float4*>(&g_thr4[h*BN + b*NN + j0]);
        const int4   te4 = *reinterpret_cast<const int4*>(&g_tie4[h*BN + b*NN + j0]);
        const float dv[4]  = {d4.x, d4.y, d4.z, d4.w};
        const float tjv[4] = {tj4.x, tj4.y, tj4.z, tj4.w};
        const int   tev[4] = {te4.x, te4.y, te4.z, te4.w};
        #pragma unroll
        for (int l = 0; l < 4; l++) {
            int j = j0 + l;
            float d = dv[l];
            bool m = (d < thri) || (d == thri && j <= tiei) ||
                     (d < tjv[l]) || (d == tjv[l] && i <= tev[l]);
            if (m) adj[l] += __expf(-d * d * inv);
        }
    }
    const float T   = thrp[0];
    const float si  = g_score[row];
    const float wti = g_w[row], wsi = g_w[BN + row], wpi = g_w[2*BN + row];
    const float4 sj  = *reinterpret_cast<const float4*>(&g_score[b*NN + j0]);
    const float4 wtj = *reinterpret_cast<const float4*>(&g_w[b*NN + j0]);
    const float4 wsj = *reinterpret_cast<const float4*>(&g_w[BN + b*NN + j0]);
    const float4 wpj = *reinterpret_cast<const float4*>(&g_w[2*BN + b*NN + j0]);
    const float4 tm4 = *reinterpret_cast<const float4*>(&tmask[(size_t)i * NN + j0]);
    const float4 sm4 = *reinterpret_cast<const float4*>(&smask[(size_t)i * NN + j0]);
    const float sjv[4]  = {sj.x, sj.y, sj.z, sj.w};
    const float wtjv[4] = {wtj.x, wtj.y, wtj.z, wtj.w};
    const float wsjv[4] = {wsj.x, wsj.y, wsj.z, wsj.w};
    const float wpjv[4] = {wpj.x, wpj.y, wpj.z, wpj.w};
    const float tmv[4]  = {tm4.x, tm4.y, tm4.z, tm4.w};
    const float smv[4]  = {sm4.x, sm4.y, sm4.z, sm4.w};
    float4 res;
    #pragma unroll
    for (int l = 0; l < 4; l++) {
        float a = adj[l] * 0.25f;
        float gate_t = tmv[l] * 0.5f * (wti + wtjv[l]);
        float gate_s = smv[l] * 0.5f * (wsi + wsjv[l]);
        float ew  = si * sjv[l];
        float e2  = exp2f(14.4269504088896341f * (T - ew));
        float den = 1.0f + e2;
        float r = __uint_as_float(0x7EF311C3u - __float_as_uint(den));
        r = r * (2.0f - den * r);
        r = r * (2.0f - den * r);
        r = r * (2.0f - den * r);
        float gate_p = r * 0.5f * (wpi + wpjv[l]);
        ((float*)&res)[l] = a * (gate_t + gate_s + gate_p);
    }
    *reinterpret_cast<float4*>(&out[roff]) = res;
}

extern "C" void kernel_launch(void* const* d_in, const int* in_sizes, int n_in,
                              void* d_out, int out_size) {
    const float* x        = (const float*)d_in[0];
    const float* proj_w   = (const float*)d_in[1];
    const float* gate_w   = (const float*)d_in[2];
    const float* gate_b   = (const float*)d_in[3];
    const float* score_w1 = (const float*)d_in[4];
    const float* score_b1 = (const float*)d_in[5];
    const float* score_w2 = (const float*)d_in[6];
    const float* score_b2 = (const float*)d_in[7];
    const float* thr      = (const float*)d_in[8];
    const float* tmask    = (const float*)d_in[9];
    const float* smask    = (const float*)d_in[10];
    float* out = (float*)d_out;

    // capture slot #3 = gram v2 (the kernel under test this round)
    prep_kernel<<<256, 256>>>(proj_w, score_w1);                  // 0
    gemm_kernel<256, true><<<dim3(4, 352), 256>>>(x, nullptr);    // 1
    gemm_kernel<128, false><<<dim3(2, 352), 256>>>(x, score_b1);  // 2
    gram_kernel<<<dim3(NTJ, NTI, 64), 256>>>();                   // 3
    select_kernel<<<dim3(BN, 4), 256>>>();                        // 4
    reduce_kernel<<<4, 256>>>();                                  // 5
    score_kernel<<<BN, 128>>>(score_w2, score_b2);                // 6
    gate_kernel<<<BN / 8, 256>>>(x, gate_w, gate_b);              // 7
    combine_kernel<<<dim3(NN, BATCH), 352>>>(out, tmask, smask, thr); // 8
}

// round 14
// speedup vs baseline: 1.1153x; 1.1153x over previous
#include <cuda_runtime.h>
#include <cstdint>

#define BATCH 16
#define NN 1408
#define DIM 256
#define HD 64
#define BN (BATCH*NN)
#define KSEL 211
#define NT 22
#define NPB (NT*NT*BATCH*4)
#define SZ ((size_t)BATCH*NN*NN)

typedef unsigned long long u64;

__device__ __align__(16) float g_z[(size_t)BN*DIM];
__device__ __align__(16) float g_h1[(size_t)BN*128];
__device__ __align__(16) float g_sq[4*BN];
__device__ __align__(16) float g_dist4[4*SZ];
__device__ __align__(16) float g_thr4[4*BN];
__device__ __align__(16) int   g_tie4[4*BN];
__device__ __align__(16) float g_score[BN];
__device__ __align__(16) float g_w[3*BN];
__device__ __align__(16) float g_projT[DIM*DIM];
__device__ __align__(16) float g_w1T[DIM*128];
__device__ __align__(16) float g_partial[NPB];
__device__ float g_inv4[4];   // holds -log2(e)/(2*mean^2+1e-8)

__device__ __forceinline__ u64 pack2(float lo, float hi){
    u64 r; asm("mov.b64 %0, {%1, %2};" : "=l"(r) : "f"(lo), "f"(hi)); return r;
}
__device__ __forceinline__ u64 fma2(u64 a, u64 b, u64 c){
    u64 d; asm("fma.rn.f32x2 %0, %1, %2, %3;" : "=l"(d) : "l"(a), "l"(b), "l"(c)); return d;
}
__device__ __forceinline__ float2 unpack2(u64 v){
    float2 f; asm("mov.b64 {%0, %1}, %2;" : "=f"(f.x), "=f"(f.y) : "l"(v)); return f;
}

__global__ void prep_kernel(const float* __restrict__ proj_w,
                            const float* __restrict__ score_w1) {
    int idx = blockIdx.x * 256 + threadIdx.x;
    int c = idx >> 8, k = idx & 255;
    g_projT[k * DIM + c] = proj_w[idx];
    if (idx < 128 * 256) g_w1T[k * 128 + c] = score_w1[idx];
}

template<int NOUT, bool IS_Z>
__global__ void __launch_bounds__(256, 4) gemm_kernel(const float* __restrict__ A,
                                                      const float* __restrict__ bias) {
    const float* Bt = IS_Z ? g_projT : g_w1T;
    float*       C  = IS_Z ? g_z     : g_h1;
    __shared__ __align__(16) float As[32][68];
    __shared__ __align__(16) float Bs[32][68];
    const int t = threadIdx.x, tx = t & 15, ty = t >> 4;
    const int m0 = blockIdx.y * 64, n0 = blockIdx.x * 64;
    u64 acc[4][2] = {};
    for (int k0 = 0; k0 < DIM; k0 += 32) {
        #pragma unroll
        for (int i = 0; i < 8; i++) {
            int e = t + i * 256, r = e >> 5, k = e & 31;
            As[k][r] = A[(size_t)(m0 + r) * DIM + k0 + k];
        }
        #pragma unroll
        for (int i = 0; i < 8; i++) {
            int e = t + i * 256, c = e & 63, k = e >> 6;
            Bs[k][c] = Bt[(size_t)(k0 + k) * NOUT + n0 + c];
        }
        __syncthreads();
        #pragma unroll 8
        for (int k = 0; k < 32; k++) {
            float4 bf = *reinterpret_cast<const float4*>(&Bs[k][tx*4]);
            float4 af = *reinterpret_cast<const float4*>(&As[k][ty*4]);
            u64 b01 = pack2(bf.x, bf.y), b23 = pack2(bf.z, bf.w);
            const float av[4] = {af.x, af.y, af.z, af.w};
            #pragma unroll
            for (int i = 0; i < 4; i++) {
                u64 aa = pack2(av[i], av[i]);
                acc[i][0] = fma2(aa, b01, acc[i][0]);
                acc[i][1] = fma2(aa, b23, acc[i][1]);
            }
        }
        __syncthreads();
    }
    #pragma unroll
    for (int i = 0; i < 4; i++) {
        float2 v01 = unpack2(acc[i][0]), v23 = unpack2(acc[i][1]);
        float v[4] = {v01.x, v01.y, v23.x, v23.y};
        float4 o;
        #pragma unroll
        for (int j = 0; j < 4; j++) {
            float val = v[j];
            if (!IS_Z) {
                val += bias[n0 + tx*4 + j];
                val = 0.5f * val * (1.0f + erff(val * 0.70710678118654752f));
            }
            ((float*)&o)[j] = val;
        }
        *reinterpret_cast<float4*>(&C[(size_t)(m0 + ty*4 + i) * NOUT + n0 + tx*4]) = o;
        if (IS_Z) {
            float sq = v[0]*v[0] + v[1]*v[1] + v[2]*v[2] + v[3]*v[3];
            #pragma unroll
            for (int off = 8; off; off >>= 1)
                sq += __shfl_down_sync(0xffffffffu, sq, off, 16);
            if (tx == 0) g_sq[blockIdx.x * BN + m0 + ty*4 + i] = sq;
        }
    }
}

__global__ void score_kernel(const float* __restrict__ w2, const float* __restrict__ b2) {
    const int n = blockIdx.x, t = threadIdx.x;
    float s = g_h1[(size_t)n * 128 + t] * w2[t];
    #pragma unroll
    for (int off = 16; off; off >>= 1) s += __shfl_down_sync(0xffffffffu, s, off);
    __shared__ float sw[4];
    if ((t & 31) == 0) sw[t >> 5] = s;
    __syncthreads();
    if (t == 0) {
        float v = sw[0] + sw[1] + sw[2] + sw[3] + b2[0];
        g_score[n] = 1.0f / (1.0f + expf(-v));
    }
}

__global__ void gate_kernel(const float* __restrict__ x, const float* __restrict__ gw,
                            const float* __restrict__ gb) {
    const int lane = threadIdx.x & 31;
    const int n = blockIdx.x * 8 + (threadIdx.x >> 5);
    const float* xr = x + (size_t)n * DIM;
    float a0 = 0.f, a1 = 0.f, a2 = 0.f;
    for (int k = lane; k < DIM; k += 32) {
        float xv = xr[k];
        a0 += xv * gw[k]; a1 += xv * gw[DIM + k]; a2 += xv * gw[2*DIM + k];
    }
    #pragma unroll
    for (int off = 16; off; off >>= 1) {
        a0 += __shfl_down_sync(0xffffffffu, a0, off);
        a1 += __shfl_down_sync(0xffffffffu, a1, off);
        a2 += __shfl_down_sync(0xffffffffu, a2, off);
    }
    if (lane == 0) {
        float p0 = a0 + gb[0], p1 = a1 + gb[1], p2 = a2 + gb[2];
        float mx = fmaxf(p0, fmaxf(p1, p2));
        float e0 = expf(p0 - mx), e1 = expf(p1 - mx), e2 = expf(p2 - mx);
        float es = e0 + e1 + e2;
        float pr[3] = {e0/es, e1/es, e2/es};
        int pos[3];
        #pragma unroll
        for (int a = 0; a < 3; a++) {
            int c = 0;
            #pragma unroll
            for (int b = 0; b < 3; b++)
                c += ((pr[b] > pr[a]) || (pr[b] == pr[a] && b < a)) ? 1 : 0;
            pos[a] = c;
        }
        float sp[3];
        #pragma unroll
        for (int a = 0; a < 3; a++) sp[pos[a]] = pr[a];
        float c1 = sp[0] + sp[1];
        float c2 = c1 + sp[2];
        if (!((c1 - sp[1]) < 0.85f)) sp[1] = 0.f;
        if (!((c2 - sp[2]) < 0.85f)) sp[2] = 0.f;
        float w0 = sp[pos[0]], w1 = sp[pos[1]], w2v = sp[pos[2]];
        float scale = 1.0f / (w0 + w1 + w2v + 1e-8f);
        g_w[n]        = w0  * scale;
        g_w[BN + n]   = w1  * scale;
        g_w[2*BN + n] = w2v * scale;
    }
}

// gram v1 (proven component of the 1133.6us best config)
__global__ void __launch_bounds__(256, 4) gram_kernel() {
    const int tj = blockIdx.x, ti = blockIdx.y;
    const int z = blockIdx.z, h = z >> 4, b = z & 15;
    const int pidx = z * (NT*NT) + ti*NT + tj;
    if (tj < ti) { if (threadIdx.x == 0) g_partial[pidx] = 0.f; return; }
    __shared__ __align__(16) float Az[64][68];
    __shared__ __align__(16) float Bz[64][68];
    __shared__ float sred[8];
    const int t = threadIdx.x, tx = t & 15, ty = t >> 4;
    const int i0 = ti*64, j0 = tj*64;
    const float* zb = g_z + (size_t)b * NN * DIM + h * HD;
    #pragma unroll
    for (int i = 0; i < 16; i++) {
        int e = t + i * 256, k = e & 63, r = e >> 6;
        Az[k][r] = zb[(size_t)(i0 + r) * DIM + k];
        Bz[k][r] = zb[(size_t)(j0 + r) * DIM + k];
    }
    __syncthreads();
    u64 acc[4][2] = {};
    #pragma unroll 16
    for (int k = 0; k < 64; k++) {
        float4 bf = *reinterpret_cast<const float4*>(&Bz[k][tx*4]);
        float4 af = *reinterpret_cast<const float4*>(&Az[k][ty*4]);
        u64 b01 = pack2(bf.x, bf.y), b23 = pack2(bf.z, bf.w);
        const float av[4] = {af.x, af.y, af.z, af.w};
        #pragma unroll
        for (int i = 0; i < 4; i++) {
            u64 aa = pack2(av[i], av[i]);
            acc[i][0] = fma2(aa, b01, acc[i][0]);
            acc[i][1] = fma2(aa, b23, acc[i][1]);
        }
    }
    const float* sqb = g_sq + h * BN + b * NN;
    float* dbase = g_dist4 + (size_t)h * SZ + (size_t)b * NN * NN;
    float lsum = 0.f;
    float dval[4][4];
    #pragma unroll
    for (int i = 0; i < 4; i++) {
        float sqi = sqb[i0 + ty*4 + i];
        float2 v01 = unpack2(acc[i][0]), v23 = unpack2(acc[i][1]);
        float dot[4] = {v01.x, v01.y, v23.x, v23.y};
        #pragma unroll
        for (int j = 0; j < 4; j++) {
            float d2 = sqi + sqb[j0 + tx*4 + j] - 2.0f * dot[j];
            float dv = (d2 > 0.f) ? sqrtf(d2) : 0.f;
            dval[i][j] = dv;
            lsum += dv;
        }
        *reinterpret_cast<float4*>(&dbase[(size_t)(i0 + ty*4 + i) * NN + j0 + tx*4]) =
            make_float4(dval[i][0], dval[i][1], dval[i][2], dval[i][3]);
    }
    #pragma unroll
    for (int off = 16; off; off >>= 1) lsum += __shfl_down_sync(0xffffffffu, lsum, off);
    if ((t & 31) == 0) sred[t >> 5] = lsum;
    if (tj > ti) {
        __syncthreads();
        #pragma unroll
        for (int i = 0; i < 4; i++)
            #pragma unroll
            for (int j = 0; j < 4; j++)
                Az[tx*4 + j][ty*4 + i] = dval[i][j];
        __syncthreads();
        #pragma unroll
        for (int it = 0; it < 16; it++) {
            int e = t + it * 256, c = e & 63, r = e >> 6;
            dbase[(size_t)(j0 + r) * NN + i0 + c] = Az[r][c];
        }
    } else {
        __syncthreads();
    }
    if (t == 0) {
        float s = 0.f;
        #pragma unroll
        for (int wv = 0; wv < 8; wv++) s += sred[wv];
        g_partial[pidx] = (tj > ti) ? 2.0f * s : s;
    }
}

__global__ void reduce_kernel() {
    const int h = blockIdx.x;
    __shared__ float s[256];
    float a = 0.f;
    for (int i = threadIdx.x; i < NT*NT*BATCH; i += 256)
        a += g_partial[h * (NT*NT*BATCH) + i];
    s[threadIdx.x] = a;
    __syncthreads();
    for (int off = 128; off; off >>= 1) {
        if (threadIdx.x < off) s[threadIdx.x] += s[threadIdx.x + off];
        __syncthreads();
    }
    if (threadIdx.x == 0) {
        float mean = s[0] / 31719424.0f;
        float inv = 1.0f / (2.0f * mean * mean + 1e-8f);
        g_inv4[h] = -1.4426950408889634f * inv;   // pre-scaled for exp2f in combine
    }
}

// hist8 radix select v2 (R11: 408us)
__global__ void select_kernel() {
    __shared__ unsigned rowv[NN];
    __shared__ unsigned hist8[8][256];
    __shared__ unsigned wsum[8];
    __shared__ int sh[4];
    const int t = threadIdx.x, w = t >> 5, lane = t & 31;
    const int row = blockIdx.x;
    const int h = 3 - blockIdx.y;
    const float* dp = g_dist4 + (size_t)h * SZ + (size_t)row * NN;
    unsigned myv[6];
    #pragma unroll
    for (int i = 0; i < 6; i++) {
        int j = t + i * 256;
        unsigned u = (j < NN) ? __float_as_uint(dp[j]) : 0xFFFFFFFFu;
        myv[i] = u;
        if (j < NN) rowv[j] = u;
    }
    #pragma unroll
    for (int i = 0; i < 8; i++) hist8[i][t] = 0;
    __syncthreads();
    unsigned prefix = 0; int rem = KSEL, ceq = 0;
    #pragma unroll
    for (int pass = 0; pass < 4; pass++) {
        const int shift = 24 - 8 * pass;
        const unsigned himask = pass ? (0xFFFFFFFFu << (shift + 8)) : 0u;
        #pragma unroll
        for (int i = 0; i < 6; i++) {
            unsigned u = myv[i];
            if (((u & himask) == prefix) && (t + i * 256 < NN))
                atomicAdd(&hist8[w][(u >> shift) & 255u], 1u);
        }
        __syncthreads();
        unsigned hv[8], v = 0;
        #pragma unroll
        for (int i = 0; i < 8; i++) { hv[i] = hist8[i][t]; v += hv[i]; }
        if (v) {
            #pragma unroll
            for (int i = 0; i < 8; i++) if (hv[i]) hist8[i][t] = 0;
        }
        unsigned incl = v;
        #pragma unroll
        for (int o = 1; o < 32; o <<= 1) {
            unsigned nb = __shfl_up_sync(0xffffffffu, incl, o);
            if (lane >= o) incl += nb;
        }
        if (lane == 31) wsum[w] = incl;
        __syncthreads();
        unsigned wo = 0;
        #pragma unroll
        for (int i = 0; i < 8; i++) if (i < w) wo += wsum[i];
        incl += wo;
        unsigned excl = incl - v;
        if (excl < (unsigned)rem && (unsigned)rem <= incl) {
            sh[0] = t; sh[1] = rem - (int)excl; sh[2] = (int)v;
        }
        __syncthreads();
        prefix |= ((unsigned)sh[0]) << shift;
        rem = sh[1]; ceq = sh[2];
    }
    int tieIdx;
    if (rem >= ceq) {
        tieIdx = 0x7fffffff;
    } else {
        if (t == 0) {
            int c = 0, tiv = NN;
            for (int j = 0; j < NN; j++)
                if (rowv[j] == prefix) { if (++c == rem) { tiv = j; break; } }
            sh[3] = tiv;
        }
        __syncthreads();
        tieIdx = sh[3];
    }
    if (t == 0) { g_thr4[h*BN + row] = __uint_as_float(prefix); g_tie4[h*BN + row] = tieIdx; }
}

__global__ void combine_kernel(float* __restrict__ out,
                               const float* __restrict__ tmask,
                               const float* __restrict__ smask,
                               const float* __restrict__ thrp) {
    const int i = blockIdx.x, b = blockIdx.y;
    const int row = b * NN + i;
    const int j0 = threadIdx.x * 4;
    const size_t roff = (size_t)b * NN * NN + (size_t)i * NN + j0;
    float adj[4] = {0.f, 0.f, 0.f, 0.f};
    #pragma unroll
    for (int h = 0; h < 4; h++) {
        const float inv2n = g_inv4[h];                  // -log2e/(2*mean^2+eps)
        const float thri = g_thr4[h*BN + row];
        const int   tiei = g_tie4[h*BN + row];
        const float4 d4  = *reinterpret_cast<const float4*>(&g_dist4[(size_t)h * SZ + roff]);
        const float4 tj4 = *reinterpret_cast<const float4*>(&g_thr4[h*BN + b*NN + j0]);
        const int4   te4 = *reinterpret_cast<const int4*>(&g_tie4[h*BN + b*NN + j0]);
        const float dv[4]  = {d4.x, d4.y, d4.z, d4.w};
        const float tjv[4] = {tj4.x, tj4.y, tj4.z, tj4.w};
        const int   tev[4] = {te4.x, te4.y, te4.z, te4.w};
        #pragma unroll
        for (int l = 0; l < 4; l++) {
            int j = j0 + l;
            float d = dv[l];
            bool m = (d < thri) || (d == thri && j <= tiei) ||
                     (d < tjv[l]) || (d == tjv[l] && i <= tev[l]);
            if (m) adj[l] += exp2f(d * d * inv2n);
        }
    }
    const float T   = thrp[0];
    const float si  = g_score[row];
    const float wti = g_w[row], wsi = g_w[BN + row], wpi = g_w[2*BN + row];
    const float4 sj  = *reinterpret_cast<const float4*>(&g_score[b*NN + j0]);
    const float4 wtj = *reinterpret_cast<const float4*>(&g_w[b*NN + j0]);
    const float4 wsj = *reinterpret_cast<const float4*>(&g_w[BN + b*NN + j0]);
    const float4 wpj = *reinterpret_cast<const float4*>(&g_w[2*BN + b*NN + j0]);
    const float4 tm4 = *reinterpret_cast<const float4*>(&tmask[(size_t)i * NN + j0]);
    const float4 sm4 = *reinterpret_cast<const float4*>(&smask[(size_t)i * NN + j0]);
    const float sjv[4]  = {sj.x, sj.y, sj.z, sj.w};
    const float wtjv[4] = {wtj.x, wtj.y, wtj.z, wtj.w};
    const float wsjv[4] = {wsj.x, wsj.y, wsj.z, wsj.w};
    const float wpjv[4] = {wpj.x, wpj.y, wpj.z, wpj.w};
    const float tmv[4]  = {tm4.x, tm4.y, tm4.z, tm4.w};
    const float smv[4]  = {sm4.x, sm4.y, sm4.z, sm4.w};
    float4 res;
    #pragma unroll
    for (int l = 0; l < 4; l++) {
        float a = adj[l] * 0.25f;
        float gate_t = tmv[l] * 0.5f * (wti + wtjv[l]);
        float gate_s = smv[l] * 0.5f * (wsi + wsjv[l]);
        float ew  = si * sjv[l];
        float e2  = exp2f(14.4269504088896341f * (T - ew));
        float den = 1.0f + e2;
        float r = __uint_as_float(0x7EF311C3u - __float_as_uint(den));
        r = r * (2.0f - den * r);
        r = r * (2.0f - den * r);
        r = r * (2.0f - den * r);
        float gate_p = r * 0.5f * (wpi + wpjv[l]);
        ((float*)&res)[l] = a * (gate_t + gate_s + gate_p);
    }
    *reinterpret_cast<float4*>(&out[roff]) = res;
}

extern "C" void kernel_launch(void* const* d_in, const int* in_sizes, int n_in,
                              void* d_out, int out_size) {
    const float* x        = (const float*)d_in[0];
    const float* proj_w   = (const float*)d_in[1];
    const float* gate_w   = (const float*)d_in[2];
    const float* gate_b   = (const float*)d_in[3];
    const float* score_w1 = (const float*)d_in[4];
    const float* score_b1 = (const float*)d_in[5];
    const float* score_w2 = (const float*)d_in[6];
    const float* score_b2 = (const float*)d_in[7];
    const float* thr      = (const float*)d_in[8];
    const float* tmask    = (const float*)d_in[9];
    const float* smask    = (const float*)d_in[10];
    float* out = (float*)d_out;

    // capture slot #3 = gram v1 (first direct measurement since the LDS128 change)
    prep_kernel<<<256, 256>>>(proj_w, score_w1);                  // 0
    gemm_kernel<256, true><<<dim3(4, 352), 256>>>(x, nullptr);    // 1
    gemm_kernel<128, false><<<dim3(2, 352), 256>>>(x, score_b1);  // 2
    gram_kernel<<<dim3(NT, NT, 64), 256>>>();                     // 3
    select_kernel<<<dim3(BN, 4), 256>>>();                        // 4
    reduce_kernel<<<4, 256>>>();                                  // 5
    score_kernel<<<BN, 128>>>(score_w2, score_b2);                // 6
    gate_kernel<<<BN / 8, 256>>>(x, gate_w, gate_b);              // 7
    combine_kernel<<<dim3(NN, BATCH), 352>>>(out, tmask, smask, thr); // 8
}

// round 15
// speedup vs baseline: 1.1198x; 1.0040x over previous
#include <cuda_runtime.h>
#include <cstdint>

#define BATCH 16
#define NN 1408
#define DIM 256
#define HD 64
#define BN (BATCH*NN)
#define KSEL 211
#define NT 22
#define NPB (NT*NT*BATCH*4)
#define SZ ((size_t)BATCH*NN*NN)

typedef unsigned long long u64;

__device__ __align__(16) float g_z[(size_t)BN*DIM];
__device__ __align__(16) float g_h1[(size_t)BN*128];
__device__ __align__(16) float g_sq[4*BN];
__device__ __align__(16) float g_dist4[4*SZ];
__device__ __align__(16) float g_thr4[4*BN];
__device__ __align__(16) int   g_tie4[4*BN];
__device__ __align__(16) float g_score[BN];
__device__ __align__(16) float g_w[3*BN];
__device__ __align__(16) float g_projT[DIM*DIM];
__device__ __align__(16) float g_w1T[DIM*128];
__device__ __align__(16) float g_partial[NPB];
__device__ float g_inv4[4];   // holds -log2(e)/(2*mean^2+1e-8)

__device__ __forceinline__ u64 pack2(float lo, float hi){
    u64 r; asm("mov.b64 %0, {%1, %2};" : "=l"(r) : "f"(lo), "f"(hi)); return r;
}
__device__ __forceinline__ u64 fma2(u64 a, u64 b, u64 c){
    u64 d; asm("fma.rn.f32x2 %0, %1, %2, %3;" : "=l"(d) : "l"(a), "l"(b), "l"(c)); return d;
}
__device__ __forceinline__ float2 unpack2(u64 v){
    float2 f; asm("mov.b64 {%0, %1}, %2;" : "=f"(f.x), "=f"(f.y) : "l"(v)); return f;
}

__global__ void prep_kernel(const float* __restrict__ proj_w,
                            const float* __restrict__ score_w1) {
    int idx = blockIdx.x * 256 + threadIdx.x;
    int c = idx >> 8, k = idx & 255;
    g_projT[k * DIM + c] = proj_w[idx];
    if (idx < 128 * 256) g_w1T[k * 128 + c] = score_w1[idx];
}

template<int NOUT, bool IS_Z>
__global__ void __launch_bounds__(256, 4) gemm_kernel(const float* __restrict__ A,
                                                      const float* __restrict__ bias) {
    const float* Bt = IS_Z ? g_projT : g_w1T;
    float*       C  = IS_Z ? g_z     : g_h1;
    __shared__ __align__(16) float As[32][68];
    __shared__ __align__(16) float Bs[32][68];
    const int t = threadIdx.x, tx = t & 15, ty = t >> 4;
    const int m0 = blockIdx.y * 64, n0 = blockIdx.x * 64;
    u64 acc[4][2] = {};
    for (int k0 = 0; k0 < DIM; k0 += 32) {
        #pragma unroll
        for (int i = 0; i < 8; i++) {
            int e = t + i * 256, r = e >> 5, k = e & 31;
            As[k][r] = A[(size_t)(m0 + r) * DIM + k0 + k];
        }
        #pragma unroll
        for (int i = 0; i < 8; i++) {
            int e = t + i * 256, c = e & 63, k = e >> 6;
            Bs[k][c] = Bt[(size_t)(k0 + k) * NOUT + n0 + c];
        }
        __syncthreads();
        #pragma unroll 8
        for (int k = 0; k < 32; k++) {
            float4 bf = *reinterpret_cast<const float4*>(&Bs[k][tx*4]);
            float4 af = *reinterpret_cast<const float4*>(&As[k][ty*4]);
            u64 b01 = pack2(bf.x, bf.y), b23 = pack2(bf.z, bf.w);
            const float av[4] = {af.x, af.y, af.z, af.w};
            #pragma unroll
            for (int i = 0; i < 4; i++) {
                u64 aa = pack2(av[i], av[i]);
                acc[i][0] = fma2(aa, b01, acc[i][0]);
                acc[i][1] = fma2(aa, b23, acc[i][1]);
            }
        }
        __syncthreads();
    }
    #pragma unroll
    for (int i = 0; i < 4; i++) {
        float2 v01 = unpack2(acc[i][0]), v23 = unpack2(acc[i][1]);
        float v[4] = {v01.x, v01.y, v23.x, v23.y};
        float4 o;
        #pragma unroll
        for (int j = 0; j < 4; j++) {
            float val = v[j];
            if (!IS_Z) {
                val += bias[n0 + tx*4 + j];
                val = 0.5f * val * (1.0f + erff(val * 0.70710678118654752f));
            }
            ((float*)&o)[j] = val;
        }
        *reinterpret_cast<float4*>(&C[(size_t)(m0 + ty*4 + i) * NOUT + n0 + tx*4]) = o;
        if (IS_Z) {
            float sq = v[0]*v[0] + v[1]*v[1] + v[2]*v[2] + v[3]*v[3];
            #pragma unroll
            for (int off = 8; off; off >>= 1)
                sq += __shfl_down_sync(0xffffffffu, sq, off, 16);
            if (tx == 0) g_sq[blockIdx.x * BN + m0 + ty*4 + i] = sq;
        }
    }
}

__global__ void score_kernel(const float* __restrict__ w2, const float* __restrict__ b2) {
    const int n = blockIdx.x, t = threadIdx.x;
    float s = g_h1[(size_t)n * 128 + t] * w2[t];
    #pragma unroll
    for (int off = 16; off; off >>= 1) s += __shfl_down_sync(0xffffffffu, s, off);
    __shared__ float sw[4];
    if ((t & 31) == 0) sw[t >> 5] = s;
    __syncthreads();
    if (t == 0) {
        float v = sw[0] + sw[1] + sw[2] + sw[3] + b2[0];
        g_score[n] = 1.0f / (1.0f + expf(-v));
    }
}

__global__ void gate_kernel(const float* __restrict__ x, const float* __restrict__ gw,
                            const float* __restrict__ gb) {
    const int lane = threadIdx.x & 31;
    const int n = blockIdx.x * 8 + (threadIdx.x >> 5);
    const float* xr = x + (size_t)n * DIM;
    float a0 = 0.f, a1 = 0.f, a2 = 0.f;
    for (int k = lane; k < DIM; k += 32) {
        float xv = xr[k];
        a0 += xv * gw[k]; a1 += xv * gw[DIM + k]; a2 += xv * gw[2*DIM + k];
    }
    #pragma unroll
    for (int off = 16; off; off >>= 1) {
        a0 += __shfl_down_sync(0xffffffffu, a0, off);
        a1 += __shfl_down_sync(0xffffffffu, a1, off);
        a2 += __shfl_down_sync(0xffffffffu, a2, off);
    }
    if (lane == 0) {
        float p0 = a0 + gb[0], p1 = a1 + gb[1], p2 = a2 + gb[2];
        float mx = fmaxf(p0, fmaxf(p1, p2));
        float e0 = expf(p0 - mx), e1 = expf(p1 - mx), e2 = expf(p2 - mx);
        float es = e0 + e1 + e2;
        float pr[3] = {e0/es, e1/es, e2/es};
        int pos[3];
        #pragma unroll
        for (int a = 0; a < 3; a++) {
            int c = 0;
            #pragma unroll
            for (int b = 0; b < 3; b++)
                c += ((pr[b] > pr[a]) || (pr[b] == pr[a] && b < a)) ? 1 : 0;
            pos[a] = c;
        }
        float sp[3];
        #pragma unroll
        for (int a = 0; a < 3; a++) sp[pos[a]] = pr[a];
        float c1 = sp[0] + sp[1];
        float c2 = c1 + sp[2];
        if (!((c1 - sp[1]) < 0.85f)) sp[1] = 0.f;
        if (!((c2 - sp[2]) < 0.85f)) sp[2] = 0.f;
        float w0 = sp[pos[0]], w1 = sp[pos[1]], w2v = sp[pos[2]];
        float scale = 1.0f / (w0 + w1 + w2v + 1e-8f);
        g_w[n]        = w0  * scale;
        g_w[BN + n]   = w1  * scale;
        g_w[2*BN + n] = w2v * scale;
    }
}

// gram v1 + conflict-free mirror epilogue (diagonal-skewed staging)
__global__ void __launch_bounds__(256, 4) gram_kernel() {
    const int tj = blockIdx.x, ti = blockIdx.y;
    const int z = blockIdx.z, h = z >> 4, b = z & 15;
    const int pidx = z * (NT*NT) + ti*NT + tj;
    if (tj < ti) { if (threadIdx.x == 0) g_partial[pidx] = 0.f; return; }
    __shared__ __align__(16) float Az[64][68];
    __shared__ __align__(16) float Bz[64][68];
    __shared__ float sred[8];
    const int t = threadIdx.x, tx = t & 15, ty = t >> 4;
    const int i0 = ti*64, j0 = tj*64;
    const float* zb = g_z + (size_t)b * NN * DIM + h * HD;
    #pragma unroll
    for (int i = 0; i < 16; i++) {
        int e = t + i * 256, k = e & 63, r = e >> 6;
        Az[k][r] = zb[(size_t)(i0 + r) * DIM + k];
        Bz[k][r] = zb[(size_t)(j0 + r) * DIM + k];
    }
    __syncthreads();
    u64 acc[4][2] = {};
    #pragma unroll 16
    for (int k = 0; k < 64; k++) {
        float4 bf = *reinterpret_cast<const float4*>(&Bz[k][tx*4]);
        float4 af = *reinterpret_cast<const float4*>(&Az[k][ty*4]);
        u64 b01 = pack2(bf.x, bf.y), b23 = pack2(bf.z, bf.w);
        const float av[4] = {af.x, af.y, af.z, af.w};
        #pragma unroll
        for (int i = 0; i < 4; i++) {
            u64 aa = pack2(av[i], av[i]);
            acc[i][0] = fma2(aa, b01, acc[i][0]);
            acc[i][1] = fma2(aa, b23, acc[i][1]);
        }
    }
    const float* sqb = g_sq + h * BN + b * NN;
    float* dbase = g_dist4 + (size_t)h * SZ + (size_t)b * NN * NN;
    float lsum = 0.f;
    float dval[4][4];
    #pragma unroll
    for (int i = 0; i < 4; i++) {
        float sqi = sqb[i0 + ty*4 + i];
        float2 v01 = unpack2(acc[i][0]), v23 = unpack2(acc[i][1]);
        float dot[4] = {v01.x, v01.y, v23.x, v23.y};
        #pragma unroll
        for (int j = 0; j < 4; j++) {
            float d2 = sqi + sqb[j0 + tx*4 + j] - 2.0f * dot[j];
            float dv = (d2 > 0.f) ? sqrtf(d2) : 0.f;
            dval[i][j] = dv;
            lsum += dv;
        }
        *reinterpret_cast<float4*>(&dbase[(size_t)(i0 + ty*4 + i) * NN + j0 + tx*4]) =
            make_float4(dval[i][0], dval[i][1], dval[i][2], dval[i][3]);
    }
    #pragma unroll
    for (int off = 16; off; off >>= 1) lsum += __shfl_down_sync(0xffffffffu, lsum, off);
    if ((t & 31) == 0) sred[t >> 5] = lsum;
    if (tj > ti) {
        __syncthreads();                 // all compute reads of Az done
        // stage natural layout with diagonal skew: Mz[rr][(cc+rr)&63], stride 68
        float* Mz = &Az[0][0];
        #pragma unroll
        for (int i = 0; i < 4; i++) {
            int rr = ty*4 + i;
            #pragma unroll
            for (int j = 0; j < 4; j++) {
                int cc = tx*4 + j;
                Mz[rr*68 + ((cc + rr) & 63)] = dval[i][j];
            }
        }
        __syncthreads();
        // mirror write: reads conflict-free (bank = 5*rr+cc mod 32), STG coalesced
        #pragma unroll
        for (int it = 0; it < 16; it++) {
            int e = t + it * 256;        // [0,4096)
            int rr = e & 63, cc = e >> 6;
            float v = Mz[rr*68 + ((cc + rr) & 63)];
            dbase[(size_t)(j0 + cc) * NN + i0 + rr] = v;
        }
    } else {
        __syncthreads();
    }
    if (t == 0) {
        float s = 0.f;
        #pragma unroll
        for (int wv = 0; wv < 8; wv++) s += sred[wv];
        g_partial[pidx] = (tj > ti) ? 2.0f * s : s;
    }
}

__global__ void reduce_kernel() {
    const int h = blockIdx.x;
    __shared__ float s[256];
    float a = 0.f;
    for (int i = threadIdx.x; i < NT*NT*BATCH; i += 256)
        a += g_partial[h * (NT*NT*BATCH) + i];
    s[threadIdx.x] = a;
    __syncthreads();
    for (int off = 128; off; off >>= 1) {
        if (threadIdx.x < off) s[threadIdx.x] += s[threadIdx.x + off];
        __syncthreads();
    }
    if (threadIdx.x == 0) {
        float mean = s[0] / 31719424.0f;
        float inv = 1.0f / (2.0f * mean * mean + 1e-8f);
        g_inv4[h] = -1.4426950408889634f * inv;
    }
}

// hist8 radix select v2 (R11: 408us)
__global__ void select_kernel() {
    __shared__ unsigned rowv[NN];
    __shared__ unsigned hist8[8][256];
    __shared__ unsigned wsum[8];
    __shared__ int sh[4];
    const int t = threadIdx.x, w = t >> 5, lane = t & 31;
    const int row = blockIdx.x;
    const int h = 3 - blockIdx.y;
    const float* dp = g_dist4 + (size_t)h * SZ + (size_t)row * NN;
    unsigned myv[6];
    #pragma unroll
    for (int i = 0; i < 6; i++) {
        int j = t + i * 256;
        unsigned u = (j < NN) ? __float_as_uint(dp[j]) : 0xFFFFFFFFu;
        myv[i] = u;
        if (j < NN) rowv[j] = u;
    }
    #pragma unroll
    for (int i = 0; i < 8; i++) hist8[i][t] = 0;
    __syncthreads();
    unsigned prefix = 0; int rem = KSEL, ceq = 0;
    #pragma unroll
    for (int pass = 0; pass < 4; pass++) {
        const int shift = 24 - 8 * pass;
        const unsigned himask = pass ? (0xFFFFFFFFu << (shift + 8)) : 0u;
        #pragma unroll
        for (int i = 0; i < 6; i++) {
            unsigned u = myv[i];
            if (((u & himask) == prefix) && (t + i * 256 < NN))
                atomicAdd(&hist8[w][(u >> shift) & 255u], 1u);
        }
        __syncthreads();
        unsigned hv[8], v = 0;
        #pragma unroll
        for (int i = 0; i < 8; i++) { hv[i] = hist8[i][t]; v += hv[i]; }
        if (v) {
            #pragma unroll
            for (int i = 0; i < 8; i++) if (hv[i]) hist8[i][t] = 0;
        }
        unsigned incl = v;
        #pragma unroll
        for (int o = 1; o < 32; o <<= 1) {
            unsigned nb = __shfl_up_sync(0xffffffffu, incl, o);
            if (lane >= o) incl += nb;
        }
        if (lane == 31) wsum[w] = incl;
        __syncthreads();
        unsigned wo = 0;
        #pragma unroll
        for (int i = 0; i < 8; i++) if (i < w) wo += wsum[i];
        incl += wo;
        unsigned excl = incl - v;
        if (excl < (unsigned)rem && (unsigned)rem <= incl) {
            sh[0] = t; sh[1] = rem - (int)excl; sh[2] = (int)v;
        }
        __syncthreads();
        prefix |= ((unsigned)sh[0]) << shift;
        rem = sh[1]; ceq = sh[2];
    }
    int tieIdx;
    if (rem >= ceq) {
        tieIdx = 0x7fffffff;
    } else {
        if (t == 0) {
            int c = 0, tiv = NN;
            for (int j = 0; j < NN; j++)
                if (rowv[j] == prefix) { if (++c == rem) { tiv = j; break; } }
            sh[3] = tiv;
        }
        __syncthreads();
        tieIdx = sh[3];
    }
    if (t == 0) { g_thr4[h*BN + row] = __uint_as_float(prefix); g_tie4[h*BN + row] = tieIdx; }
}

__global__ void combine_kernel(float* __restrict__ out,
                               const float* __restrict__ tmask,
                               const float* __restrict__ smask,
                               const float* __restrict__ thrp) {
    const int i = blockIdx.x, b = blockIdx.y;
    const int row = b * NN + i;
    const int j0 = threadIdx.x * 4;
    const size_t roff = (size_t)b * NN * NN + (size_t)i * NN + j0;
    float adj[4] = {0.f, 0.f, 0.f, 0.f};
    #pragma unroll
    for (int h = 0; h < 4; h++) {
        const float inv2n = g_inv4[h];
        const float thri = g_thr4[h*BN + row];
        const int   tiei = g_tie4[h*BN + row];
        const float4 d4  = *reinterpret_cast<const float4*>(&g_dist4[(size_t)h * SZ + roff]);
        const float4 tj4 = *reinterpret_cast<const float4*>(&g_thr4[h*BN + b*NN + j0]);
        const int4   te4 = *reinterpret_cast<const int4*>(&g_tie4[h*BN + b*NN + j0]);
        const float dv[4]  = {d4.x, d4.y, d4.z, d4.w};
        const float tjv[4] = {tj4.x, tj4.y, tj4.z, tj4.w};
        const int   tev[4] = {te4.x, te4.y, te4.z, te4.w};
        #pragma unroll
        for (int l = 0; l < 4; l++) {
            int j = j0 + l;
            float d = dv[l];
            bool m = (d < thri) || (d == thri && j <= tiei) ||
                     (d < tjv[l]) || (d == tjv[l] && i <= tev[l]);
            if (m) adj[l] += exp2f(d * d * inv2n);
        }
    }
    const float T   = thrp[0];
    const float si  = g_score[row];
    const float wti = g_w[row], wsi = g_w[BN + row], wpi = g_w[2*BN + row];
    const float4 sj  = *reinterpret_cast<const float4*>(&g_score[b*NN + j0]);
    const float4 wtj = *reinterpret_cast<const float4*>(&g_w[b*NN + j0]);
    const float4 wsj = *reinterpret_cast<const float4*>(&g_w[BN + b*NN + j0]);
    const float4 wpj = *reinterpret_cast<const float4*>(&g_w[2*BN + b*NN + j0]);
    const float4 tm4 = *reinterpret_cast<const float4*>(&tmask[(size_t)i * NN + j0]);
    const float4 sm4 = *reinterpret_cast<const float4*>(&smask[(size_t)i * NN + j0]);
    const float sjv[4]  = {sj.x, sj.y, sj.z, sj.w};
    const float wtjv[4] = {wtj.x, wtj.y, wtj.z, wtj.w};
    const float wsjv[4] = {wsj.x, wsj.y, wsj.z, wsj.w};
    const float wpjv[4] = {wpj.x, wpj.y, wpj.z, wpj.w};
    const float tmv[4]  = {tm4.x, tm4.y, tm4.z, tm4.w};
    const float smv[4]  = {sm4.x, sm4.y, sm4.z, sm4.w};
    float4 res;
    #pragma unroll
    for (int l = 0; l < 4; l++) {
        float a = adj[l] * 0.25f;
        float gate_t = tmv[l] * 0.5f * (wti + wtjv[l]);
        float gate_s = smv[l] * 0.5f * (wsi + wsjv[l]);
        float ew  = si * sjv[l];
        float e2  = exp2f(14.4269504088896341f * (T - ew));
        float den = 1.0f + e2;
        float r = __uint_as_float(0x7EF311C3u - __float_as_uint(den));
        r = r * (2.0f - den * r);
        r = r * (2.0f - den * r);
        r = r * (2.0f - den * r);
        float gate_p = r * 0.5f * (wpi + wpjv[l]);
        ((float*)&res)[l] = a * (gate_t + gate_s + gate_p);
    }
    *reinterpret_cast<float4*>(&out[roff]) = res;
}

extern "C" void kernel_launch(void* const* d_in, const int* in_sizes, int n_in,
                              void* d_out, int out_size) {
    const float* x        = (const float*)d_in[0];
    const float* proj_w   = (const float*)d_in[1];
    const float* gate_w   = (const float*)d_in[2];
    const float* gate_b   = (const float*)d_in[3];
    const float* score_w1 = (const float*)d_in[4];
    const float* score_b1 = (const float*)d_in[5];
    const float* score_w2 = (const float*)d_in[6];
    const float* score_b2 = (const float*)d_in[7];
    const float* thr      = (const float*)d_in[8];
    const float* tmask    = (const float*)d_in[9];
    const float* smask    = (const float*)d_in[10];
    float* out = (float*)d_out;

    // capture slot #3 = gram (verify the mirror-staging fix: 304us baseline)
    prep_kernel<<<256, 256>>>(proj_w, score_w1);                  // 0
    gemm_kernel<256, true><<<dim3(4, 352), 256>>>(x, nullptr);    // 1
    gemm_kernel<128, false><<<dim3(2, 352), 256>>>(x, score_b1);  // 2
    gram_kernel<<<dim3(NT, NT, 64), 256>>>();                     // 3
    select_kernel<<<dim3(BN, 4), 256>>>();                        // 4
    reduce_kernel<<<4, 256>>>();                                  // 5
    score_kernel<<<BN, 128>>>(score_w2, score_b2);                // 6
    gate_kernel<<<BN / 8, 256>>>(x, gate_w, gate_b);              // 7
    combine_kernel<<<dim3(NN, BATCH), 352>>>(out, tmask, smask, thr); // 8
}

// round 16
// speedup vs baseline: 1.1371x; 1.0155x over previous
#include <cuda_runtime.h>
#include <cstdint>

#define BATCH 16
#define NN 1408
#define DIM 256
#define HD 64
#define BN (BATCH*NN)
#define KSEL 211
#define NTI 11
#define NTJ 22
#define NPB (NTI*NTJ*BATCH*4)
#define SZ ((size_t)BATCH*NN*NN)

typedef unsigned long long u64;

__device__ __align__(16) float g_z[(size_t)BN*DIM];
__device__ __align__(16) float g_h1[(size_t)BN*128];
__device__ __align__(16) float g_sq[4*BN];
__device__ __align__(16) float g_dist4[4*SZ];
__device__ __align__(16) float g_thr4[4*BN];
__device__ __align__(16) int   g_tie4[4*BN];
__device__ __align__(16) float g_score[BN];
__device__ __align__(16) float g_w[3*BN];
__device__ __align__(16) float g_projT[DIM*DIM];
__device__ __align__(16) float g_w1T[DIM*128];
__device__ __align__(16) float g_partial[NPB];
__device__ float g_inv4[4];   // holds -log2(e)/(2*mean^2+1e-8)

__device__ __forceinline__ u64 pack2(float lo, float hi){
    u64 r; asm("mov.b64 %0, {%1, %2};" : "=l"(r) : "f"(lo), "f"(hi)); return r;
}
__device__ __forceinline__ u64 fma2(u64 a, u64 b, u64 c){
    u64 d; asm("fma.rn.f32x2 %0, %1, %2, %3;" : "=l"(d) : "l"(a), "l"(b), "l"(c)); return d;
}
__device__ __forceinline__ float2 unpack2(u64 v){
    float2 f; asm("mov.b64 {%0, %1}, %2;" : "=f"(f.x), "=f"(f.y) : "l"(v)); return f;
}

__global__ void prep_kernel(const float* __restrict__ proj_w,
                            const float* __restrict__ score_w1) {
    int idx = blockIdx.x * 256 + threadIdx.x;
    int c = idx >> 8, k = idx & 255;
    g_projT[k * DIM + c] = proj_w[idx];
    if (idx < 128 * 256) g_w1T[k * 128 + c] = score_w1[idx];
}

template<int NOUT, bool IS_Z>
__global__ void __launch_bounds__(256, 4) gemm_kernel(const float* __restrict__ A,
                                                      const float* __restrict__ bias) {
    const float* Bt = IS_Z ? g_projT : g_w1T;
    float*       C  = IS_Z ? g_z     : g_h1;
    __shared__ __align__(16) float As[32][68];
    __shared__ __align__(16) float Bs[32][68];
    const int t = threadIdx.x, tx = t & 15, ty = t >> 4;
    const int m0 = blockIdx.y * 64, n0 = blockIdx.x * 64;
    u64 acc[4][2] = {};
    for (int k0 = 0; k0 < DIM; k0 += 32) {
        #pragma unroll
        for (int i = 0; i < 8; i++) {
            int e = t + i * 256, r = e >> 5, k = e & 31;
            As[k][r] = A[(size_t)(m0 + r) * DIM + k0 + k];
        }
        #pragma unroll
        for (int i = 0; i < 8; i++) {
            int e = t + i * 256, c = e & 63, k = e >> 6;
            Bs[k][c] = Bt[(size_t)(k0 + k) * NOUT + n0 + c];
        }
        __syncthreads();
        #pragma unroll 8
        for (int k = 0; k < 32; k++) {
            float4 bf = *reinterpret_cast<const float4*>(&Bs[k][tx*4]);
            float4 af = *reinterpret_cast<const float4*>(&As[k][ty*4]);
            u64 b01 = pack2(bf.x, bf.y), b23 = pack2(bf.z, bf.w);
            const float av[4] = {af.x, af.y, af.z, af.w};
            #pragma unroll
            for (int i = 0; i < 4; i++) {
                u64 aa = pack2(av[i], av[i]);
                acc[i][0] = fma2(aa, b01, acc[i][0]);
                acc[i][1] = fma2(aa, b23, acc[i][1]);
            }
        }
        __syncthreads();
    }
    #pragma unroll
    for (int i = 0; i < 4; i++) {
        float2 v01 = unpack2(acc[i][0]), v23 = unpack2(acc[i][1]);
        float v[4] = {v01.x, v01.y, v23.x, v23.y};
        float4 o;
        #pragma unroll
        for (int j = 0; j < 4; j++) {
            float val = v[j];
            if (!IS_Z) {
                val += bias[n0 + tx*4 + j];
                val = 0.5f * val * (1.0f + erff(val * 0.70710678118654752f));
            }
            ((float*)&o)[j] = val;
        }
        *reinterpret_cast<float4*>(&C[(size_t)(m0 + ty*4 + i) * NOUT + n0 + tx*4]) = o;
        if (IS_Z) {
            float sq = v[0]*v[0] + v[1]*v[1] + v[2]*v[2] + v[3]*v[3];
            #pragma unroll
            for (int off = 8; off; off >>= 1)
                sq += __shfl_down_sync(0xffffffffu, sq, off, 16);
            if (tx == 0) g_sq[blockIdx.x * BN + m0 + ty*4 + i] = sq;
        }
    }
}

__global__ void score_kernel(const float* __restrict__ w2, const float* __restrict__ b2) {
    const int n = blockIdx.x, t = threadIdx.x;
    float s = g_h1[(size_t)n * 128 + t] * w2[t];
    #pragma unroll
    for (int off = 16; off; off >>= 1) s += __shfl_down_sync(0xffffffffu, s, off);
    __shared__ float sw[4];
    if ((t & 31) == 0) sw[t >> 5] = s;
    __syncthreads();
    if (t == 0) {
        float v = sw[0] + sw[1] + sw[2] + sw[3] + b2[0];
        g_score[n] = 1.0f / (1.0f + expf(-v));
    }
}

__global__ void gate_kernel(const float* __restrict__ x, const float* __restrict__ gw,
                            const float* __restrict__ gb) {
    const int lane = threadIdx.x & 31;
    const int n = blockIdx.x * 8 + (threadIdx.x >> 5);
    const float* xr = x + (size_t)n * DIM;
    float a0 = 0.f, a1 = 0.f, a2 = 0.f;
    for (int k = lane; k < DIM; k += 32) {
        float xv = xr[k];
        a0 += xv * gw[k]; a1 += xv * gw[DIM + k]; a2 += xv * gw[2*DIM + k];
    }
    #pragma unroll
    for (int off = 16; off; off >>= 1) {
        a0 += __shfl_down_sync(0xffffffffu, a0, off);
        a1 += __shfl_down_sync(0xffffffffu, a1, off);
        a2 += __shfl_down_sync(0xffffffffu, a2, off);
    }
    if (lane == 0) {
        float p0 = a0 + gb[0], p1 = a1 + gb[1], p2 = a2 + gb[2];
        float mx = fmaxf(p0, fmaxf(p1, p2));
        float e0 = expf(p0 - mx), e1 = expf(p1 - mx), e2 = expf(p2 - mx);
        float es = e0 + e1 + e2;
        float pr[3] = {e0/es, e1/es, e2/es};
        int pos[3];
        #pragma unroll
        for (int a = 0; a < 3; a++) {
            int c = 0;
            #pragma unroll
            for (int b = 0; b < 3; b++)
                c += ((pr[b] > pr[a]) || (pr[b] == pr[a] && b < a)) ? 1 : 0;
            pos[a] = c;
        }
        float sp[3];
        #pragma unroll
        for (int a = 0; a < 3; a++) sp[pos[a]] = pr[a];
        float c1 = sp[0] + sp[1];
        float c2 = c1 + sp[2];
        if (!((c1 - sp[1]) < 0.85f)) sp[1] = 0.f;
        if (!((c2 - sp[2]) < 0.85f)) sp[2] = 0.f;
        float w0 = sp[pos[0]], w1 = sp[pos[1]], w2v = sp[pos[2]];
        float scale = 1.0f / (w0 + w1 + w2v + 1e-8f);
        g_w[n]        = w0  * scale;
        g_w[BN + n]   = w1  * scale;
        g_w[2*BN + n] = w2v * scale;
    }
}

// gram v3: 128(i)x64(j) tile, 8x4/thread. Coalesced [k][r] fills (v1-style),
// regs kept <=64 by restructured epilogue, skewed conflict-free mirror staging.
__global__ void __launch_bounds__(256, 4) gram_kernel() {
    const int tj = blockIdx.x, ti = blockIdx.y;
    const int z = blockIdx.z, h = z >> 4, b = z & 15;
    const int pidx = z * (NTI*NTJ) + ti * NTJ + tj;
    if (tj < 2*ti) { if (threadIdx.x == 0) g_partial[pidx] = 0.f; return; }
    __shared__ __align__(16) float Az[64*132];   // [k][r], r<128, stride 132
    __shared__ __align__(16) float Bz[64*68];    // [k][c], c<64, stride 68
    __shared__ float sred[8];
    const int t = threadIdx.x, tx = t & 15, ty = t >> 4;
    const int i0 = ti*128, j0 = tj*64;
    const float* zb = g_z + (size_t)b * NN * DIM + h * HD;
    #pragma unroll
    for (int it = 0; it < 32; it++) {
        int e = t + it * 256, k = e & 63, r = e >> 6;
        Az[k*132 + r] = zb[(size_t)(i0 + r) * DIM + k];
    }
    #pragma unroll
    for (int it = 0; it < 16; it++) {
        int e = t + it * 256, k = e & 63, c = e >> 6;
        Bz[k*68 + c] = zb[(size_t)(j0 + c) * DIM + k];
    }
    __syncthreads();
    u64 acc[8][2] = {};
    #pragma unroll 8
    for (int k = 0; k < 64; k++) {
        float4 bf = *reinterpret_cast<const float4*>(&Bz[k*68 + tx*4]);
        float4 a0 = *reinterpret_cast<const float4*>(&Az[k*132 + ty*8]);
        float4 a1 = *reinterpret_cast<const float4*>(&Az[k*132 + ty*8 + 4]);
        u64 b01 = pack2(bf.x, bf.y), b23 = pack2(bf.z, bf.w);
        const float av[8] = {a0.x,a0.y,a0.z,a0.w,a1.x,a1.y,a1.z,a1.w};
        #pragma unroll
        for (int i = 0; i < 8; i++) {
            u64 aa = pack2(av[i], av[i]);
            acc[i][0] = fma2(aa, b01, acc[i][0]);
            acc[i][1] = fma2(aa, b23, acc[i][1]);
        }
    }
    __syncthreads();                 // Az reads done; Az reusable as staging
    const float* sqb = g_sq + h * BN + b * NN;
    float* dbase = g_dist4 + (size_t)h * SZ + (size_t)b * NN * NN;
    const bool pure = (tj >= 2*ti + 2);
    float sqj[4];
    #pragma unroll
    for (int j = 0; j < 4; j++) sqj[j] = sqb[j0 + tx*4 + j];
    float lsum = 0.f;
    float* Mz = Az;                  // staging: Mz[rr(0..63)][(cc+rr)&127], stride 132
    #pragma unroll
    for (int i = 0; i < 8; i++) {
        int cc = ty*8 + i;
        int gi = i0 + cc;
        float sqi = sqb[gi];
        float2 v01 = unpack2(acc[i][0]), v23 = unpack2(acc[i][1]);
        float dv[4];
        float d2;
        d2 = sqi + sqj[0] - 2.0f * v01.x; dv[0] = (d2 > 0.f) ? sqrtf(d2) : 0.f;
        d2 = sqi + sqj[1] - 2.0f * v01.y; dv[1] = (d2 > 0.f) ? sqrtf(d2) : 0.f;
        d2 = sqi + sqj[2] - 2.0f * v23.x; dv[2] = (d2 > 0.f) ? sqrtf(d2) : 0.f;
        d2 = sqi + sqj[3] - 2.0f * v23.y; dv[3] = (d2 > 0.f) ? sqrtf(d2) : 0.f;
        if (pure) {
            lsum += 2.0f * (dv[0] + dv[1] + dv[2] + dv[3]);
            *reinterpret_cast<float4*>(&dbase[(size_t)gi * NN + j0 + tx*4]) =
                make_float4(dv[0], dv[1], dv[2], dv[3]);
        } else {
            #pragma unroll
            for (int j = 0; j < 4; j++) {
                int gj = j0 + tx*4 + j;
                float wgt = (gj > gi) ? 2.0f : ((gj == gi) ? 1.0f : 0.0f);
                lsum += wgt * dv[j];
                if (gj >= gi) dbase[(size_t)gi * NN + gj] = dv[j];
            }
        }
        #pragma unroll
        for (int jj = 0; jj < 4; jj++) {
            int rr = tx*4 + jj;
            Mz[rr*132 + ((cc + rr) & 127)] = dv[jj];
        }
    }
    #pragma unroll
    for (int off = 16; off; off >>= 1) lsum += __shfl_down_sync(0xffffffffu, lsum, off);
    if ((t & 31) == 0) sred[t >> 5] = lsum;
    __syncthreads();                 // staging + sred visible
    #pragma unroll
    for (int it = 0; it < 32; it++) {
        int e = t + it * 256;        // [0,8192)
        int cc = e & 127, rr = e >> 7;
        float v = Mz[rr*132 + ((cc + rr) & 127)];
        int dstRow = j0 + rr, dstCol = i0 + cc;
        if (pure || dstRow > dstCol)
            dbase[(size_t)dstRow * NN + dstCol] = v;
    }
    if (t == 0) {
        float s = 0.f;
        #pragma unroll
        for (int wv = 0; wv < 8; wv++) s += sred[wv];
        g_partial[pidx] = s;
    }
}

__global__ void reduce_kernel() {
    const int h = blockIdx.x;
    __shared__ float s[256];
    float a = 0.f;
    for (int i = threadIdx.x; i < NTI*NTJ*BATCH; i += 256)
        a += g_partial[h * (NTI*NTJ*BATCH) + i];
    s[threadIdx.x] = a;
    __syncthreads();
    for (int off = 128; off; off >>= 1) {
        if (threadIdx.x < off) s[threadIdx.x] += s[threadIdx.x + off];
        __syncthreads();
    }
    if (threadIdx.x == 0) {
        float mean = s[0] / 31719424.0f;
        float inv = 1.0f / (2.0f * mean * mean + 1e-8f);
        g_inv4[h] = -1.4426950408889634f * inv;
    }
}

// hist8 radix select v2 (R11: 408us)
__global__ void select_kernel() {
    __shared__ unsigned rowv[NN];
    __shared__ unsigned hist8[8][256];
    __shared__ unsigned wsum[8];
    __shared__ int sh[4];
    const int t = threadIdx.x, w = t >> 5, lane = t & 31;
    const int row = blockIdx.x;
    const int h = 3 - blockIdx.y;
    const float* dp = g_dist4 + (size_t)h * SZ + (size_t)row * NN;
    unsigned myv[6];
    #pragma unroll
    for (int i = 0; i < 6; i++) {
        int j = t + i * 256;
        unsigned u = (j < NN) ? __float_as_uint(dp[j]) : 0xFFFFFFFFu;
        myv[i] = u;
        if (j < NN) rowv[j] = u;
    }
    #pragma unroll
    for (int i = 0; i < 8; i++) hist8[i][t] = 0;
    __syncthreads();
    unsigned prefix = 0; int rem = KSEL, ceq = 0;
    #pragma unroll
    for (int pass = 0; pass < 4; pass++) {
        const int shift = 24 - 8 * pass;
        const unsigned himask = pass ? (0xFFFFFFFFu << (shift + 8)) : 0u;
        #pragma unroll
        for (int i = 0; i < 6; i++) {
            unsigned u = myv[i];
            if (((u & himask) == prefix) && (t + i * 256 < NN))
                atomicAdd(&hist8[w][(u >> shift) & 255u], 1u);
        }
        __syncthreads();
        unsigned hv[8], v = 0;
        #pragma unroll
        for (int i = 0; i < 8; i++) { hv[i] = hist8[i][t]; v += hv[i]; }
        if (v) {
            #pragma unroll
            for (int i = 0; i < 8; i++) if (hv[i]) hist8[i][t] = 0;
        }
        unsigned incl = v;
        #pragma unroll
        for (int o = 1; o < 32; o <<= 1) {
            unsigned nb = __shfl_up_sync(0xffffffffu, incl, o);
            if (lane >= o) incl += nb;
        }
        if (lane == 31) wsum[w] = incl;
        __syncthreads();
        unsigned wo = 0;
        #pragma unroll
        for (int i = 0; i < 8; i++) if (i < w) wo += wsum[i];
        incl += wo;
        unsigned excl = incl - v;
        if (excl < (unsigned)rem && (unsigned)rem <= incl) {
            sh[0] = t; sh[1] = rem - (int)excl; sh[2] = (int)v;
        }
        __syncthreads();
        prefix |= ((unsigned)sh[0]) << shift;
        rem = sh[1]; ceq = sh[2];
    }
    int tieIdx;
    if (rem >= ceq) {
        tieIdx = 0x7fffffff;
    } else {
        if (t == 0) {
            int c = 0, tiv = NN;
            for (int j = 0; j < NN; j++)
                if (rowv[j] == prefix) { if (++c == rem) { tiv = j; break; } }
            sh[3] = tiv;
        }
        __syncthreads();
        tieIdx = sh[3];
    }
    if (t == 0) { g_thr4[h*BN + row] = __uint_as_float(prefix); g_tie4[h*BN + row] = tieIdx; }
}

__global__ void combine_kernel(float* __restrict__ out,
                               const float* __restrict__ tmask,
                               const float* __restrict__ smask,
                               const float* __restrict__ thrp) {
    const int i = blockIdx.x, b = blockIdx.y;
    const int row = b * NN + i;
    const int j0 = threadIdx.x * 4;
    const size_t roff = (size_t)b * NN * NN + (size_t)i * NN + j0;
    float adj[4] = {0.f, 0.f, 0.f, 0.f};
    #pragma unroll
    for (int h = 0; h < 4; h++) {
        const float inv2n = g_inv4[h];
        const float thri = g_thr4[h*BN + row];
        const int   tiei = g_tie4[h*BN + row];
        const float4 d4  = *reinterpret_cast<const float4*>(&g_dist4[(size_t)h * SZ + roff]);
        const float4 tj4 = *reinterpret_cast<const float4*>(&g_thr4[h*BN + b*NN + j0]);
        const int4   te4 = *reinterpret_cast<const int4*>(&g_tie4[h*BN + b*NN + j0]);
        const float dv[4]  = {d4.x, d4.y, d4.z, d4.w};
        const float tjv[4] = {tj4.x, tj4.y, tj4.z, tj4.w};
        const int   tev[4] = {te4.x, te4.y, te4.z, te4.w};
        #pragma unroll
        for (int l = 0; l < 4; l++) {
            int j = j0 + l;
            float d = dv[l];
            bool m = (d < thri) || (d == thri && j <= tiei) ||
                     (d < tjv[l]) || (d == tjv[l] && i <= tev[l]);
            if (m) adj[l] += exp2f(d * d * inv2n);
        }
    }
    const float T   = thrp[0];
    const float si  = g_score[row];
    const float wti = g_w[row], wsi = g_w[BN + row], wpi = g_w[2*BN + row];
    const float4 sj  = *reinterpret_cast<const float4*>(&g_score[b*NN + j0]);
    const float4 wtj = *reinterpret_cast<const float4*>(&g_w[b*NN + j0]);
    const float4 wsj = *reinterpret_cast<const float4*>(&g_w[BN + b*NN + j0]);
    const float4 wpj = *reinterpret_cast<const float4*>(&g_w[2*BN + b*NN + j0]);
    const float4 tm4 = *reinterpret_cast<const float4*>(&tmask[(size_t)i * NN + j0]);
    const float4 sm4 = *reinterpret_cast<const float4*>(&smask[(size_t)i * NN + j0]);
    const float sjv[4]  = {sj.x, sj.y, sj.z, sj.w};
    const float wtjv[4] = {wtj.x, wtj.y, wtj.z, wtj.w};
    const float wsjv[4] = {wsj.x, wsj.y, wsj.z, wsj.w};
    const float wpjv[4] = {wpj.x, wpj.y, wpj.z, wpj.w};
    const float tmv[4]  = {tm4.x, tm4.y, tm4.z, tm4.w};
    const float smv[4]  = {sm4.x, sm4.y, sm4.z, sm4.w};
    float4 res;
    #pragma unroll
    for (int l = 0; l < 4; l++) {
        float a = adj[l] * 0.25f;
        float gate_t = tmv[l] * 0.5f * (wti + wtjv[l]);
        float gate_s = smv[l] * 0.5f * (wsi + wsjv[l]);
        float ew  = si * sjv[l];
        float e2  = exp2f(14.4269504088896341f * (T - ew));
        float den = 1.0f + e2;
        float r = __uint_as_float(0x7EF311C3u - __float_as_uint(den));
        r = r * (2.0f - den * r);
        r = r * (2.0f - den * r);
        r = r * (2.0f - den * r);
        float gate_p = r * 0.5f * (wpi + wpjv[l]);
        ((float*)&res)[l] = a * (gate_t + gate_s + gate_p);
    }
    *reinterpret_cast<float4*>(&out[roff]) = res;
}

extern "C" void kernel_launch(void* const* d_in, const int* in_sizes, int n_in,
                              void* d_out, int out_size) {
    const float* x        = (const float*)d_in[0];
    const float* proj_w   = (const float*)d_in[1];
    const float* gate_w   = (const float*)d_in[2];
    const float* gate_b   = (const float*)d_in[3];
    const float* score_w1 = (const float*)d_in[4];
    const float* score_b1 = (const float*)d_in[5];
    const float* score_w2 = (const float*)d_in[6];
    const float* score_b2 = (const float*)d_in[7];
    const float* thr      = (const float*)d_in[8];
    const float* tmask    = (const float*)d_in[9];
    const float* smask    = (const float*)d_in[10];
    float* out = (float*)d_out;

    // capture slot #3 = gram v3 (verify vs 297us v1 baseline)
    prep_kernel<<<256, 256>>>(proj_w, score_w1);                  // 0
    gemm_kernel<256, true><<<dim3(4, 352), 256>>>(x, nullptr);    // 1
    gemm_kernel<128, false><<<dim3(2, 352), 256>>>(x, score_b1);  // 2
    gram_kernel<<<dim3(NTJ, NTI, 64), 256>>>();                   // 3
    select_kernel<<<dim3(BN, 4), 256>>>();                        // 4
    reduce_kernel<<<4, 256>>>();                                  // 5
    score_kernel<<<BN, 128>>>(score_w2, score_b2);                // 6
    gate_kernel<<<BN / 8, 256>>>(x, gate_w, gate_b);              // 7
    combine_kernel<<<dim3(NN, BATCH), 352>>>(out, tmask, smask, thr); // 8
}

// round 17
// speedup vs baseline: 1.2034x; 1.0583x over previous
#include <cuda_runtime.h>
#include <cstdint>

#define BATCH 16
#define NN 1408
#define DIM 256
#define HD 64
#define BN (BATCH*NN)
#define KSEL 211
#define NTI 11
#define NTJ 22
#define NPB (NTI*NTJ*BATCH*4)
#define SZ ((size_t)BATCH*NN*NN)

typedef unsigned long long u64;

__device__ __align__(16) float g_z[(size_t)BN*DIM];
__device__ __align__(16) float g_h1[(size_t)BN*128];
__device__ __align__(16) float g_sq[4*BN];
__device__ __align__(16) float g_dist4[4*SZ];
__device__ __align__(16) float g_thr4[4*BN];
__device__ __align__(16) int   g_tie4[4*BN];
__device__ __align__(16) float g_score[BN];
__device__ __align__(16) float g_w[3*BN];
__device__ __align__(16) float g_projT[DIM*DIM];
__device__ __align__(16) float g_w1T[DIM*128];
__device__ __align__(16) float g_partial[NPB];
__device__ float g_inv4[4];   // holds -log2(e)/(2*mean^2+1e-8)

__device__ __forceinline__ u64 pack2(float lo, float hi){
    u64 r; asm("mov.b64 %0, {%1, %2};" : "=l"(r) : "f"(lo), "f"(hi)); return r;
}
__device__ __forceinline__ u64 fma2(u64 a, u64 b, u64 c){
    u64 d; asm("fma.rn.f32x2 %0, %1, %2, %3;" : "=l"(d) : "l"(a), "l"(b), "l"(c)); return d;
}
__device__ __forceinline__ float2 unpack2(u64 v){
    float2 f; asm("mov.b64 {%0, %1}, %2;" : "=f"(f.x), "=f"(f.y) : "l"(v)); return f;
}

__global__ void prep_kernel(const float* __restrict__ proj_w,
                            const float* __restrict__ score_w1) {
    int idx = blockIdx.x * 256 + threadIdx.x;
    int c = idx >> 8, k = idx & 255;
    g_projT[k * DIM + c] = proj_w[idx];
    if (idx < 128 * 256) g_w1T[k * 128 + c] = score_w1[idx];
}

template<int NOUT, bool IS_Z>
__global__ void __launch_bounds__(256, 4) gemm_kernel(const float* __restrict__ A,
                                                      const float* __restrict__ bias) {
    const float* Bt = IS_Z ? g_projT : g_w1T;
    float*       C  = IS_Z ? g_z     : g_h1;
    __shared__ __align__(16) float As[32][68];
    __shared__ __align__(16) float Bs[32][68];
    const int t = threadIdx.x, tx = t & 15, ty = t >> 4;
    const int m0 = blockIdx.y * 64, n0 = blockIdx.x * 64;
    u64 acc[4][2] = {};
    for (int k0 = 0; k0 < DIM; k0 += 32) {
        #pragma unroll
        for (int i = 0; i < 8; i++) {
            int e = t + i * 256, r = e >> 5, k = e & 31;
            As[k][r] = A[(size_t)(m0 + r) * DIM + k0 + k];
        }
        #pragma unroll
        for (int i = 0; i < 8; i++) {
            int e = t + i * 256, c = e & 63, k = e >> 6;
            Bs[k][c] = Bt[(size_t)(k0 + k) * NOUT + n0 + c];
        }
        __syncthreads();
        #pragma unroll 8
        for (int k = 0; k < 32; k++) {
            float4 bf = *reinterpret_cast<const float4*>(&Bs[k][tx*4]);
            float4 af = *reinterpret_cast<const float4*>(&As[k][ty*4]);
            u64 b01 = pack2(bf.x, bf.y), b23 = pack2(bf.z, bf.w);
            const float av[4] = {af.x, af.y, af.z, af.w};
            #pragma unroll
            for (int i = 0; i < 4; i++) {
                u64 aa = pack2(av[i], av[i]);
                acc[i][0] = fma2(aa, b01, acc[i][0]);
                acc[i][1] = fma2(aa, b23, acc[i][1]);
            }
        }
        __syncthreads();
    }
    #pragma unroll
    for (int i = 0; i < 4; i++) {
        float2 v01 = unpack2(acc[i][0]), v23 = unpack2(acc[i][1]);
        float v[4] = {v01.x, v01.y, v23.x, v23.y};
        float4 o;
        #pragma unroll
        for (int j = 0; j < 4; j++) {
            float val = v[j];
            if (!IS_Z) {
                val += bias[n0 + tx*4 + j];
                val = 0.5f * val * (1.0f + erff(val * 0.70710678118654752f));
            }
            ((float*)&o)[j] = val;
        }
        *reinterpret_cast<float4*>(&C[(size_t)(m0 + ty*4 + i) * NOUT + n0 + tx*4]) = o;
        if (IS_Z) {
            float sq = v[0]*v[0] + v[1]*v[1] + v[2]*v[2] + v[3]*v[3];
            #pragma unroll
            for (int off = 8; off; off >>= 1)
                sq += __shfl_down_sync(0xffffffffu, sq, off, 16);
            if (tx == 0) g_sq[blockIdx.x * BN + m0 + ty*4 + i] = sq;
        }
    }
}

__global__ void score_kernel(const float* __restrict__ w2, const float* __restrict__ b2) {
    const int n = blockIdx.x, t = threadIdx.x;
    float s = g_h1[(size_t)n * 128 + t] * w2[t];
    #pragma unroll
    for (int off = 16; off; off >>= 1) s += __shfl_down_sync(0xffffffffu, s, off);
    __shared__ float sw[4];
    if ((t & 31) == 0) sw[t >> 5] = s;
    __syncthreads();
    if (t == 0) {
        float v = sw[0] + sw[1] + sw[2] + sw[3] + b2[0];
        g_score[n] = 1.0f / (1.0f + expf(-v));
    }
}

__global__ void gate_kernel(const float* __restrict__ x, const float* __restrict__ gw,
                            const float* __restrict__ gb) {
    const int lane = threadIdx.x & 31;
    const int n = blockIdx.x * 8 + (threadIdx.x >> 5);
    const float* xr = x + (size_t)n * DIM;
    float a0 = 0.f, a1 = 0.f, a2 = 0.f;
    for (int k = lane; k < DIM; k += 32) {
        float xv = xr[k];
        a0 += xv * gw[k]; a1 += xv * gw[DIM + k]; a2 += xv * gw[2*DIM + k];
    }
    #pragma unroll
    for (int off = 16; off; off >>= 1) {
        a0 += __shfl_down_sync(0xffffffffu, a0, off);
        a1 += __shfl_down_sync(0xffffffffu, a1, off);
        a2 += __shfl_down_sync(0xffffffffu, a2, off);
    }
    if (lane == 0) {
        float p0 = a0 + gb[0], p1 = a1 + gb[1], p2 = a2 + gb[2];
        float mx = fmaxf(p0, fmaxf(p1, p2));
        float e0 = expf(p0 - mx), e1 = expf(p1 - mx), e2 = expf(p2 - mx);
        float es = e0 + e1 + e2;
        float pr[3] = {e0/es, e1/es, e2/es};
        int pos[3];
        #pragma unroll
        for (int a = 0; a < 3; a++) {
            int c = 0;
            #pragma unroll
            for (int b = 0; b < 3; b++)
                c += ((pr[b] > pr[a]) || (pr[b] == pr[a] && b < a)) ? 1 : 0;
            pos[a] = c;
        }
        float sp[3];
        #pragma unroll
        for (int a = 0; a < 3; a++) sp[pos[a]] = pr[a];
        float c1 = sp[0] + sp[1];
        float c2 = c1 + sp[2];
        if (!((c1 - sp[1]) < 0.85f)) sp[1] = 0.f;
        if (!((c2 - sp[2]) < 0.85f)) sp[2] = 0.f;
        float w0 = sp[pos[0]], w1 = sp[pos[1]], w2v = sp[pos[2]];
        float scale = 1.0f / (w0 + w1 + w2v + 1e-8f);
        g_w[n]        = w0  * scale;
        g_w[BN + n]   = w1  * scale;
        g_w[2*BN + n] = w2v * scale;
    }
}

// gram v3 (R15: 279us)
__global__ void __launch_bounds__(256, 4) gram_kernel() {
    const int tj = blockIdx.x, ti = blockIdx.y;
    const int z = blockIdx.z, h = z >> 4, b = z & 15;
    const int pidx = z * (NTI*NTJ) + ti * NTJ + tj;
    if (tj < 2*ti) { if (threadIdx.x == 0) g_partial[pidx] = 0.f; return; }
    __shared__ __align__(16) float Az[64*132];
    __shared__ __align__(16) float Bz[64*68];
    __shared__ float sred[8];
    const int t = threadIdx.x, tx = t & 15, ty = t >> 4;
    const int i0 = ti*128, j0 = tj*64;
    const float* zb = g_z + (size_t)b * NN * DIM + h * HD;
    #pragma unroll
    for (int it = 0; it < 32; it++) {
        int e = t + it * 256, k = e & 63, r = e >> 6;
        Az[k*132 + r] = zb[(size_t)(i0 + r) * DIM + k];
    }
    #pragma unroll
    for (int it = 0; it < 16; it++) {
        int e = t + it * 256, k = e & 63, c = e >> 6;
        Bz[k*68 + c] = zb[(size_t)(j0 + c) * DIM + k];
    }
    __syncthreads();
    u64 acc[8][2] = {};
    #pragma unroll 8
    for (int k = 0; k < 64; k++) {
        float4 bf = *reinterpret_cast<const float4*>(&Bz[k*68 + tx*4]);
        float4 a0 = *reinterpret_cast<const float4*>(&Az[k*132 + ty*8]);
        float4 a1 = *reinterpret_cast<const float4*>(&Az[k*132 + ty*8 + 4]);
        u64 b01 = pack2(bf.x, bf.y), b23 = pack2(bf.z, bf.w);
        const float av[8] = {a0.x,a0.y,a0.z,a0.w,a1.x,a1.y,a1.z,a1.w};
        #pragma unroll
        for (int i = 0; i < 8; i++) {
            u64 aa = pack2(av[i], av[i]);
            acc[i][0] = fma2(aa, b01, acc[i][0]);
            acc[i][1] = fma2(aa, b23, acc[i][1]);
        }
    }
    __syncthreads();
    const float* sqb = g_sq + h * BN + b * NN;
    float* dbase = g_dist4 + (size_t)h * SZ + (size_t)b * NN * NN;
    const bool pure = (tj >= 2*ti + 2);
    float sqj[4];
    #pragma unroll
    for (int j = 0; j < 4; j++) sqj[j] = sqb[j0 + tx*4 + j];
    float lsum = 0.f;
    float* Mz = Az;
    #pragma unroll
    for (int i = 0; i < 8; i++) {
        int cc = ty*8 + i;
        int gi = i0 + cc;
        float sqi = sqb[gi];
        float2 v01 = unpack2(acc[i][0]), v23 = unpack2(acc[i][1]);
        float dv[4];
        float d2;
        d2 = sqi + sqj[0] - 2.0f * v01.x; dv[0] = (d2 > 0.f) ? sqrtf(d2) : 0.f;
        d2 = sqi + sqj[1] - 2.0f * v01.y; dv[1] = (d2 > 0.f) ? sqrtf(d2) : 0.f;
        d2 = sqi + sqj[2] - 2.0f * v23.x; dv[2] = (d2 > 0.f) ? sqrtf(d2) : 0.f;
        d2 = sqi + sqj[3] - 2.0f * v23.y; dv[3] = (d2 > 0.f) ? sqrtf(d2) : 0.f;
        if (pure) {
            lsum += 2.0f * (dv[0] + dv[1] + dv[2] + dv[3]);
            *reinterpret_cast<float4*>(&dbase[(size_t)gi * NN + j0 + tx*4]) =
                make_float4(dv[0], dv[1], dv[2], dv[3]);
        } else {
            #pragma unroll
            for (int j = 0; j < 4; j++) {
                int gj = j0 + tx*4 + j;
                float wgt = (gj > gi) ? 2.0f : ((gj == gi) ? 1.0f : 0.0f);
                lsum += wgt * dv[j];
                if (gj >= gi) dbase[(size_t)gi * NN + gj] = dv[j];
            }
        }
        #pragma unroll
        for (int jj = 0; jj < 4; jj++) {
            int rr = tx*4 + jj;
            Mz[rr*132 + ((cc + rr) & 127)] = dv[jj];
        }
    }
    #pragma unroll
    for (int off = 16; off; off >>= 1) lsum += __shfl_down_sync(0xffffffffu, lsum, off);
    if ((t & 31) == 0) sred[t >> 5] = lsum;
    __syncthreads();
    #pragma unroll
    for (int it = 0; it < 32; it++) {
        int e = t + it * 256;
        int cc = e & 127, rr = e >> 7;
        float v = Mz[rr*132 + ((cc + rr) & 127)];
        int dstRow = j0 + rr, dstCol = i0 + cc;
        if (pure || dstRow > dstCol)
            dbase[(size_t)dstRow * NN + dstCol] = v;
    }
    if (t == 0) {
        float s = 0.f;
        #pragma unroll
        for (int wv = 0; wv < 8; wv++) s += sred[wv];
        g_partial[pidx] = s;
    }
}

__global__ void reduce_kernel() {
    const int h = blockIdx.x;
    __shared__ float s[256];
    float a = 0.f;
    for (int i = threadIdx.x; i < NTI*NTJ*BATCH; i += 256)
        a += g_partial[h * (NTI*NTJ*BATCH) + i];
    s[threadIdx.x] = a;
    __syncthreads();
    for (int off = 128; off; off >>= 1) {
        if (threadIdx.x < off) s[threadIdx.x] += s[threadIdx.x + off];
        __syncthreads();
    }
    if (threadIdx.x == 0) {
        float mean = s[0] / 31719424.0f;
        float inv = 1.0f / (2.0f * mean * mean + 1e-8f);
        g_inv4[h] = -1.4426950408889634f * inv;
    }
}

// hist8 radix select v2 (408us)
__global__ void select_kernel() {
    __shared__ unsigned rowv[NN];
    __shared__ unsigned hist8[8][256];
    __shared__ unsigned wsum[8];
    __shared__ int sh[4];
    const int t = threadIdx.x, w = t >> 5, lane = t & 31;
    const int row = blockIdx.x;
    const int h = 3 - blockIdx.y;
    const float* dp = g_dist4 + (size_t)h * SZ + (size_t)row * NN;
    unsigned myv[6];
    #pragma unroll
    for (int i = 0; i < 6; i++) {
        int j = t + i * 256;
        unsigned u = (j < NN) ? __float_as_uint(dp[j]) : 0xFFFFFFFFu;
        myv[i] = u;
        if (j < NN) rowv[j] = u;
    }
    #pragma unroll
    for (int i = 0; i < 8; i++) hist8[i][t] = 0;
    __syncthreads();
    unsigned prefix = 0; int rem = KSEL, ceq = 0;
    #pragma unroll
    for (int pass = 0; pass < 4; pass++) {
        const int shift = 24 - 8 * pass;
        const unsigned himask = pass ? (0xFFFFFFFFu << (shift + 8)) : 0u;
        #pragma unroll
        for (int i = 0; i < 6; i++) {
            unsigned u = myv[i];
            if (((u & himask) == prefix) && (t + i * 256 < NN))
                atomicAdd(&hist8[w][(u >> shift) & 255u], 1u);
        }
        __syncthreads();
        unsigned hv[8], v = 0;
        #pragma unroll
        for (int i = 0; i < 8; i++) { hv[i] = hist8[i][t]; v += hv[i]; }
        if (v) {
            #pragma unroll
            for (int i = 0; i < 8; i++) if (hv[i]) hist8[i][t] = 0;
        }
        unsigned incl = v;
        #pragma unroll
        for (int o = 1; o < 32; o <<= 1) {
            unsigned nb = __shfl_up_sync(0xffffffffu, incl, o);
            if (lane >= o) incl += nb;
        }
        if (lane == 31) wsum[w] = incl;
        __syncthreads();
        unsigned wo = 0;
        #pragma unroll
        for (int i = 0; i < 8; i++) if (i < w) wo += wsum[i];
        incl += wo;
        unsigned excl = incl - v;
        if (excl < (unsigned)rem && (unsigned)rem <= incl) {
            sh[0] = t; sh[1] = rem - (int)excl; sh[2] = (int)v;
        }
        __syncthreads();
        prefix |= ((unsigned)sh[0]) << shift;
        rem = sh[1]; ceq = sh[2];
    }
    int tieIdx;
    if (rem >= ceq) {
        tieIdx = 0x7fffffff;
    } else {
        if (t == 0) {
            int c = 0, tiv = NN;
            for (int j = 0; j < NN; j++)
                if (rowv[j] == prefix) { if (++c == rem) { tiv = j; break; } }
            sh[3] = tiv;
        }
        __syncthreads();
        tieIdx = sh[3];
    }
    if (t == 0) { g_thr4[h*BN + row] = __uint_as_float(prefix); g_tie4[h*BN + row] = tieIdx; }
}

// combine v3: mask via u64 packed-tuple compares (bit-exact, ~2x fewer predicates)
__global__ void combine_kernel(float* __restrict__ out,
                               const float* __restrict__ tmask,
                               const float* __restrict__ smask,
                               const float* __restrict__ thrp) {
    const int i = blockIdx.x, b = blockIdx.y;
    const int row = b * NN + i;
    const int j0 = threadIdx.x * 4;
    const size_t roff = (size_t)b * NN * NN + (size_t)i * NN + j0;
    const unsigned* thrb = (const unsigned*)g_thr4;
    const unsigned* tieb = (const unsigned*)g_tie4;
    float adj[4] = {0.f, 0.f, 0.f, 0.f};
    #pragma unroll
    for (int h = 0; h < 4; h++) {
        const float inv2n = g_inv4[h];
        const u64 kthri = ((u64)thrb[h*BN + row] << 32) | tieb[h*BN + row];
        const uint4 d4  = *reinterpret_cast<const uint4*>(&g_dist4[(size_t)h * SZ + roff]);
        const uint4 tj4 = *reinterpret_cast<const uint4*>(&thrb[h*BN + b*NN + j0]);
        const uint4 te4 = *reinterpret_cast<const uint4*>(&tieb[h*BN + b*NN + j0]);
        const unsigned db[4]  = {d4.x, d4.y, d4.z, d4.w};
        const unsigned tjv[4] = {tj4.x, tj4.y, tj4.z, tj4.w};
        const unsigned tev[4] = {te4.x, te4.y, te4.z, te4.w};
        #pragma unroll
        for (int l = 0; l < 4; l++) {
            u64 hi = (u64)db[l] << 32;
            u64 key_ij = hi | (unsigned)(j0 + l);
            u64 key_ji = hi | (unsigned)i;
            u64 kthrj  = ((u64)tjv[l] << 32) | tev[l];
            bool m = (key_ij <= kthri) || (key_ji <= kthrj);
            if (m) {
                float d = __uint_as_float(db[l]);
                adj[l] += exp2f(d * d * inv2n);
            }
        }
    }
    const float T   = thrp[0];
    const float si  = g_score[row];
    const float wti = g_w[row], wsi = g_w[BN + row], wpi = g_w[2*BN + row];
    const float4 sj  = *reinterpret_cast<const float4*>(&g_score[b*NN + j0]);
    const float4 wtj = *reinterpret_cast<const float4*>(&g_w[b*NN + j0]);
    const float4 wsj = *reinterpret_cast<const float4*>(&g_w[BN + b*NN + j0]);
    const float4 wpj = *reinterpret_cast<const float4*>(&g_w[2*BN + b*NN + j0]);
    const float4 tm4 = *reinterpret_cast<const float4*>(&tmask[(size_t)i * NN + j0]);
    const float4 sm4 = *reinterpret_cast<const float4*>(&smask[(size_t)i * NN + j0]);
    const float sjv[4]  = {sj.x, sj.y, sj.z, sj.w};
    const float wtjv[4] = {wtj.x, wtj.y, wtj.z, wtj.w};
    const float wsjv[4] = {wsj.x, wsj.y, wsj.z, wsj.w};
    const float wpjv[4] = {wpj.x, wpj.y, wpj.z, wpj.w};
    const float tmv[4]  = {tm4.x, tm4.y, tm4.z, tm4.w};
    const float smv[4]  = {sm4.x, sm4.y, sm4.z, sm4.w};
    float4 res;
    #pragma unroll
    for (int l = 0; l < 4; l++) {
        float a = adj[l] * 0.25f;
        float gate_t = tmv[l] * 0.5f * (wti + wtjv[l]);
        float gate_s = smv[l] * 0.5f * (wsi + wsjv[l]);
        float ew  = si * sjv[l];
        float e2  = exp2f(14.4269504088896341f * (T - ew));
        float den = 1.0f + e2;
        float r = __uint_as_float(0x7EF311C3u - __float_as_uint(den));
        r = r * (2.0f - den * r);
        r = r * (2.0f - den * r);
        r = r * (2.0f - den * r);
        float gate_p = r * 0.5f * (wpi + wpjv[l]);
        ((float*)&res)[l] = a * (gate_t + gate_s + gate_p);
    }
    *reinterpret_cast<float4*>(&out[roff]) = res;
}

extern "C" void kernel_launch(void* const* d_in, const int* in_sizes, int n_in,
                              void* d_out, int out_size) {
    const float* x        = (const float*)d_in[0];
    const float* proj_w   = (const float*)d_in[1];
    const float* gate_w   = (const float*)d_in[2];
    const float* gate_b   = (const float*)d_in[3];
    const float* score_w1 = (const float*)d_in[4];
    const float* score_b1 = (const float*)d_in[5];
    const float* score_w2 = (const float*)d_in[6];
    const float* score_b2 = (const float*)d_in[7];
    const float* thr      = (const float*)d_in[8];
    const float* tmask    = (const float*)d_in[9];
    const float* smask    = (const float*)d_in[10];
    float* out = (float*)d_out;

    // capture slot #3 = gram v3 (silicon canary: 279us baseline)
    prep_kernel<<<256, 256>>>(proj_w, score_w1);                  // 0
    gemm_kernel<256, true><<<dim3(4, 352), 256>>>(x, nullptr);    // 1
    gemm_kernel<128, false><<<dim3(2, 352), 256>>>(x, score_b1);  // 2
    gram_kernel<<<dim3(NTJ, NTI, 64), 256>>>();                   // 3
    select_kernel<<<dim3(BN, 4), 256>>>();                        // 4
    reduce_kernel<<<4, 256>>>();                                  // 5
    score_kernel<<<BN, 128>>>(score_w2, score_b2);                // 6
    gate_kernel<<<BN / 8, 256>>>(x, gate_w, gate_b);              // 7
    combine_kernel<<<dim3(NN, BATCH), 352>>>(out, tmask, smask, thr); // 8
}